// round 1
// baseline (speedup 1.0000x reference)
#include <cuda_runtime.h>
#include <math.h>

#define BB   16
#define CIN  512
#define TT   4096
#define EE   64
#define KK   2048
#define NPTS (BB * TT)        // 65536
#define ZLEN (NPTS * EE)      // 4194304

// ---------------- device scratch (no allocations allowed) ----------------
__device__ float g_h[ZLEN];          // projected features h[n][e], 16.8 MB
__device__ float g_enorm[KK];        // ||e_k||^2
__device__ int   g_qidx[NPTS];       // argmin codeword per point
__device__ int   g_counts[KK];       // histogram
__device__ float g_partials[512];    // per-CTA commitment partial sums

// ---------------- init: codeword norms + zero counts ----------------
__global__ void k_init(const float* __restrict__ embed) {
    int k = blockIdx.x * blockDim.x + threadIdx.x;
    if (k < KK) {
        const float4* row = (const float4*)(embed + (size_t)k * EE);
        float s = 0.f;
#pragma unroll
        for (int j = 0; j < 16; ++j) {
            float4 v = row[j];
            s += v.x * v.x + v.y * v.y + v.z * v.z + v.w * v.w;
        }
        g_enorm[k] = s;
        g_counts[k] = 0;
    }
}

// ---------------- projection GEMM: h = w @ x + b ----------------
// CTA: 256 threads, tile = 128 t x 64 e for one batch b. K-chunks of 32.
#define TILE_T 128
#define TILE_C 32

__global__ __launch_bounds__(256) void k_proj(const float* __restrict__ x,
                                              const float* __restrict__ w,
                                              const float* __restrict__ pb) {
    __shared__ float ws[TILE_C][68];       // ws[c][e]  (pad 68 keeps float4 aligned)
    __shared__ float xs[TILE_C][TILE_T];   // xs[c][t]

    int b  = blockIdx.x >> 5;              // 32 t-tiles per batch
    int t0 = (blockIdx.x & 31) * TILE_T;
    int tid = threadIdx.x;
    int te = tid & 15;                     // e-group: e = te*4 + j
    int tt = tid >> 4;                     // t base:  t = t0 + tt + i*16

    float acc[8][4];
#pragma unroll
    for (int i = 0; i < 8; ++i)
#pragma unroll
        for (int j = 0; j < 4; ++j) acc[i][j] = 0.f;

    const float* xb = x + (size_t)b * CIN * TT + t0;

    for (int c0 = 0; c0 < CIN; c0 += TILE_C) {
        // load w chunk, transposed to ws[c][e]
#pragma unroll
        for (int p = 0; p < 2; ++p) {
            int idx = tid + p * 256;       // 0..511
            int e   = idx >> 3;            // 0..63
            int f4  = idx & 7;             // 0..7
            float4 v = *(const float4*)(w + (size_t)e * CIN + c0 + f4 * 4);
            ws[f4 * 4 + 0][e] = v.x;
            ws[f4 * 4 + 1][e] = v.y;
            ws[f4 * 4 + 2][e] = v.z;
            ws[f4 * 4 + 3][e] = v.w;
        }
        // load x chunk (coalesced, t contiguous)
#pragma unroll
        for (int p = 0; p < 4; ++p) {
            int idx = tid + p * 256;       // 0..1023
            int c   = idx >> 5;            // 0..31
            int f4  = idx & 31;            // 0..31
            *(float4*)&xs[c][f4 * 4] =
                *(const float4*)(xb + (size_t)(c0 + c) * TT + f4 * 4);
        }
        __syncthreads();
#pragma unroll
        for (int c = 0; c < TILE_C; ++c) {
            float4 wv = *(const float4*)&ws[c][te * 4];
            float xv[8];
#pragma unroll
            for (int i = 0; i < 8; ++i) xv[i] = xs[c][tt + i * 16];
#pragma unroll
            for (int i = 0; i < 8; ++i) {
                acc[i][0] += xv[i] * wv.x;
                acc[i][1] += xv[i] * wv.y;
                acc[i][2] += xv[i] * wv.z;
                acc[i][3] += xv[i] * wv.w;
            }
        }
        __syncthreads();
    }

    float4 bv = *(const float4*)(pb + te * 4);
#pragma unroll
    for (int i = 0; i < 8; ++i) {
        int t = t0 + tt + i * 16;
        float4 o;
        o.x = acc[i][0] + bv.x;
        o.y = acc[i][1] + bv.y;
        o.z = acc[i][2] + bv.z;
        o.w = acc[i][3] + bv.w;
        *(float4*)(g_h + ((size_t)b * TT + t) * EE + te * 4) = o;
    }
}

// ---------------- distance argmin ----------------
// 128 threads/CTA, 1 point/thread (h in 64 regs). Codebook chunks of 128 in smem.
#define DKC 128

__global__ __launch_bounds__(128) void k_dist(const float* __restrict__ embed) {
    __shared__ float sE[DKC * EE];   // 32 KB
    __shared__ float sN[DKC];

    int n = blockIdx.x * 128 + threadIdx.x;
    float h[64];
    const float4* hp = (const float4*)(g_h + (size_t)n * EE);
#pragma unroll
    for (int j = 0; j < 16; ++j) {
        float4 v = hp[j];
        h[4 * j + 0] = v.x; h[4 * j + 1] = v.y;
        h[4 * j + 2] = v.z; h[4 * j + 3] = v.w;
    }

    float best = 3.4e38f;
    int bestk = 0;

    for (int k0 = 0; k0 < KK; k0 += DKC) {
        __syncthreads();
        const float4* src = (const float4*)(embed + (size_t)k0 * EE);
        float4* dst = (float4*)sE;
#pragma unroll
        for (int p = 0; p < 16; ++p) dst[threadIdx.x + p * 128] = src[threadIdx.x + p * 128];
        sN[threadIdx.x] = g_enorm[k0 + threadIdx.x];
        __syncthreads();

        for (int k = 0; k < DKC; ++k) {
            const float4* ep = (const float4*)(sE + k * EE);
            float a0 = 0.f, a1 = 0.f, a2 = 0.f, a3 = 0.f;
#pragma unroll
            for (int j = 0; j < 16; ++j) {
                float4 e4 = ep[j];
                a0 += h[4 * j + 0] * e4.x;
                a1 += h[4 * j + 1] * e4.y;
                a2 += h[4 * j + 2] * e4.z;
                a3 += h[4 * j + 3] * e4.w;
            }
            float score = sN[k] - 2.f * ((a0 + a1) + (a2 + a3));
            if (score < best) { best = score; bestk = k0 + k; }
        }
    }
    g_qidx[n] = bestk;
}

// ---------------- gather + transpose + reductions ----------------
// CTA: 256 threads, tile = 128 t for one batch b.
__global__ __launch_bounds__(256) void k_out(const float* __restrict__ embed,
                                             float* __restrict__ out) {
    __shared__ float zq[128][65];   // padded: conflict-free transposed reads
    __shared__ float red[8];

    int b  = blockIdx.x >> 5;
    int t0 = (blockIdx.x & 31) * 128;
    int tid = threadIdx.x;
    int tl   = tid >> 1;            // local t 0..127
    int half = tid & 1;             // which 32 of the 64 e's
    int n = b * TT + t0 + tl;
    int q = g_qidx[n];

    float lsum = 0.f;
    const float4* ep = (const float4*)(embed + (size_t)q * EE + half * 32);
    const float4* hp = (const float4*)(g_h + (size_t)n * EE + half * 32);
#pragma unroll
    for (int j = 0; j < 8; ++j) {
        float4 z = ep[j];
        float4 hh = hp[j];
        float dx = z.x - hh.x, dy = z.y - hh.y, dz = z.z - hh.z, dw = z.w - hh.w;
        lsum += dx * dx + dy * dy + dz * dz + dw * dw;
        int e = half * 32 + j * 4;
        zq[tl][e + 0] = z.x; zq[tl][e + 1] = z.y;
        zq[tl][e + 2] = z.z; zq[tl][e + 3] = z.w;
    }
    if (half == 0) atomicAdd(&g_counts[q], 1);   // int atomics: deterministic

    // warp + block reduce the commitment partial
#pragma unroll
    for (int s = 16; s > 0; s >>= 1) lsum += __shfl_down_sync(0xffffffffu, lsum, s);
    if ((tid & 31) == 0) red[tid >> 5] = lsum;
    __syncthreads();
    if (tid == 0) {
        float s = 0.f;
#pragma unroll
        for (int i = 0; i < 8; ++i) s += red[i];
        g_partials[blockIdx.x] = s;
    }

    // transposed write: out[b][e][t]
#pragma unroll
    for (int p = 0; p < 32; ++p) {
        int idx = p * 256 + tid;    // 0..8191
        int e = idx >> 7;
        int t = idx & 127;
        out[((size_t)b * EE + e) * TT + t0 + t] = zq[t][e];
    }
}

// ---------------- finalize scalars ----------------
__global__ void k_fin(float* __restrict__ out, int out_size) {
    __shared__ double sd[256];
    int tid = threadIdx.x;

    double lp = 0.0;
    for (int k = tid; k < KK; k += 256) {
        float p = (float)g_counts[k] / (float)NPTS;
        lp -= (double)(p * logf(p + 1e-10f));
    }
    sd[tid] = lp;
    __syncthreads();
    for (int s = 128; s > 0; s >>= 1) {
        if (tid < s) sd[tid] += sd[tid + s];
        __syncthreads();
    }

    if (out_size >= ZLEN + 18) {
        if (tid == 0) {
            out[ZLEN + 17] = (float)sd[0];
            double ds = 0.0;
            for (int i = 0; i < 512; ++i) ds += (double)g_partials[i];
            out[ZLEN] = (float)(0.25 * ds / ((double)NPTS * (double)EE));
        }
        if (tid >= 32 && tid < 48)
            out[ZLEN + 1 + (tid - 32)] = (float)(log(2048.0) * 4096.0);
    }
}

// ---------------- launch ----------------
extern "C" void kernel_launch(void* const* d_in, const int* in_sizes, int n_in,
                              void* d_out, int out_size) {
    const float* x  = (const float*)d_in[0];   // [B, CIN, T]
    const float* w  = (const float*)d_in[1];   // [E, CIN]
    const float* pb = (const float*)d_in[2];   // [E]
    const float* em = (const float*)d_in[3];   // [K, E]
    float* out = (float*)d_out;

    k_init<<<(KK + 255) / 256, 256>>>(em);
    k_proj<<<BB * (TT / TILE_T), 256>>>(x, w, pb);
    k_dist<<<NPTS / 128, 128>>>(em);
    k_out<<<BB * (TT / 128), 256>>>(em, out);
    k_fin<<<1, 256>>>(out, out_size);
}

// round 3
// speedup vs baseline: 1.0366x; 1.0366x over previous
#include <cuda_runtime.h>
#include <math.h>

#define BB   16
#define CIN  512
#define TT   4096
#define EE   64
#define KK   2048
#define NPTS (BB * TT)        // 65536
#define ZLEN (NPTS * EE)      // 4194304

typedef unsigned long long u64;

// packed fp32x2 FMA (Blackwell): d = a*b + c on both lanes, exact fp32
#define FMA2(d, a, b, c) \
    asm("fma.rn.f32x2 %0, %1, %2, %3;" : "=l"(d) : "l"(a), "l"(b), "l"(c))
#define BCAST2(d, s) \
    asm("mov.b64 %0, {%1, %1};" : "=l"(d) : "f"(s))

// ---------------- device scratch (no allocations allowed) ----------------
__device__ float g_h[ZLEN];          // projected features h[n][e], 16.8 MB
__device__ float g_enorm[KK];        // ||e_k||^2
__device__ int   g_qidx[NPTS];       // argmin codeword per point
__device__ int   g_counts[KK];       // histogram
__device__ float g_partials[512];    // per-CTA commitment partial sums

// ---------------- init: codeword norms + zero counts ----------------
__global__ void k_init(const float* __restrict__ embed) {
    int k = blockIdx.x * blockDim.x + threadIdx.x;
    if (k < KK) {
        const float4* row = (const float4*)(embed + (size_t)k * EE);
        float s = 0.f;
#pragma unroll
        for (int j = 0; j < 16; ++j) {
            float4 v = row[j];
            s += v.x * v.x + v.y * v.y + v.z * v.z + v.w * v.w;
        }
        g_enorm[k] = s;
        g_counts[k] = 0;
    }
}

// ---------------- projection GEMM: h = w @ x + b ----------------
// CTA: 256 threads, tile = 128 t x 64 e for one batch b. K-chunks of 32.
#define TILE_T 128
#define TILE_C 32

__global__ __launch_bounds__(256) void k_proj(const float* __restrict__ x,
                                              const float* __restrict__ w,
                                              const float* __restrict__ pb) {
    __shared__ float ws[TILE_C][68];       // ws[c][e]  (pad 68 keeps float4 aligned)
    __shared__ float xs[TILE_C][TILE_T];   // xs[c][t]

    int b  = blockIdx.x >> 5;              // 32 t-tiles per batch
    int t0 = (blockIdx.x & 31) * TILE_T;
    int tid = threadIdx.x;
    int te = tid & 15;                     // e-group: e = te*4 + j
    int tt = tid >> 4;                     // t base:  t = t0 + tt + i*16

    u64 acc2[8][2];                        // acc2[i][0]=(e0,e1), [1]=(e2,e3)
#pragma unroll
    for (int i = 0; i < 8; ++i) { acc2[i][0] = 0ull; acc2[i][1] = 0ull; }

    const float* xb = x + (size_t)b * CIN * TT + t0;

    for (int c0 = 0; c0 < CIN; c0 += TILE_C) {
        // load w chunk, transposed to ws[c][e]
#pragma unroll
        for (int p = 0; p < 2; ++p) {
            int idx = tid + p * 256;       // 0..511
            int e   = idx >> 3;            // 0..63
            int f4  = idx & 7;             // 0..7
            float4 v = *(const float4*)(w + (size_t)e * CIN + c0 + f4 * 4);
            ws[f4 * 4 + 0][e] = v.x;
            ws[f4 * 4 + 1][e] = v.y;
            ws[f4 * 4 + 2][e] = v.z;
            ws[f4 * 4 + 3][e] = v.w;
        }
        // load x chunk (coalesced, t contiguous)
#pragma unroll
        for (int p = 0; p < 4; ++p) {
            int idx = tid + p * 256;       // 0..1023
            int c   = idx >> 5;            // 0..31
            int f4  = idx & 31;            // 0..31
            *(float4*)&xs[c][f4 * 4] =
                *(const float4*)(xb + (size_t)(c0 + c) * TT + f4 * 4);
        }
        __syncthreads();
#pragma unroll
        for (int c = 0; c < TILE_C; ++c) {
            float4 wv = *(const float4*)&ws[c][te * 4];
            u64 wlo = *(u64*)&wv.x;        // (wv.x, wv.y)
            u64 whi = *(u64*)&wv.z;        // (wv.z, wv.w)
#pragma unroll
            for (int i = 0; i < 8; ++i) {
                float xv = xs[c][tt + i * 16];
                u64 xx;
                BCAST2(xx, xv);
                FMA2(acc2[i][0], xx, wlo, acc2[i][0]);
                FMA2(acc2[i][1], xx, whi, acc2[i][1]);
            }
        }
        __syncthreads();
    }

    float4 bv = *(const float4*)(pb + te * 4);
#pragma unroll
    for (int i = 0; i < 8; ++i) {
        int t = t0 + tt + i * 16;
        float2 lo = *(float2*)&acc2[i][0];
        float2 hi = *(float2*)&acc2[i][1];
        float4 o;
        o.x = lo.x + bv.x;
        o.y = lo.y + bv.y;
        o.z = hi.x + bv.z;
        o.w = hi.y + bv.w;
        *(float4*)(g_h + ((size_t)b * TT + t) * EE + te * 4) = o;
    }
}

// ---------------- distance argmin ----------------
// 128 threads/CTA, 1 point/thread (h in 32 packed u64 regs). Codebook chunks
// of 128 codewords staged in smem; packed f32x2 FMA for the dot products.
// NOTE: each ulonglong2 covers 4 floats -> 16 iterations for all 64 dims.
#define DKC 128

__global__ __launch_bounds__(128) void k_dist(const float* __restrict__ embed) {
    __shared__ float sE[DKC * EE];   // 32 KB
    __shared__ float sN[DKC];

    int n = blockIdx.x * 128 + threadIdx.x;
    u64 h2[32];                      // packed pairs (e0,e1),(e2,e3),... all 64
    const ulonglong2* hp = (const ulonglong2*)(g_h + (size_t)n * EE);
#pragma unroll
    for (int j = 0; j < 16; ++j) {
        ulonglong2 v = hp[j];
        h2[2 * j + 0] = v.x;
        h2[2 * j + 1] = v.y;
    }

    float best = 3.4e38f;
    int bestk = 0;

    for (int k0 = 0; k0 < KK; k0 += DKC) {
        __syncthreads();
        const float4* src = (const float4*)(embed + (size_t)k0 * EE);
        float4* dst = (float4*)sE;
#pragma unroll
        for (int p = 0; p < 16; ++p) dst[threadIdx.x + p * 128] = src[threadIdx.x + p * 128];
        sN[threadIdx.x] = g_enorm[k0 + threadIdx.x];
        __syncthreads();

        for (int k = 0; k < DKC; ++k) {
            const ulonglong2* ep = (const ulonglong2*)(sE + k * EE);
            u64 a0 = 0ull, a1 = 0ull, a2 = 0ull, a3 = 0ull;
#pragma unroll
            for (int j = 0; j < 16; ++j) {          // 16 x 4 floats = 64 dims
                ulonglong2 e2 = ep[j];              // LDS.128 broadcast
                if (j & 1) {
                    FMA2(a2, h2[2 * j + 0], e2.x, a2);
                    FMA2(a3, h2[2 * j + 1], e2.y, a3);
                } else {
                    FMA2(a0, h2[2 * j + 0], e2.x, a0);
                    FMA2(a1, h2[2 * j + 1], e2.y, a1);
                }
            }
            float2 f0 = *(float2*)&a0;
            float2 f1 = *(float2*)&a1;
            float2 f2 = *(float2*)&a2;
            float2 f3 = *(float2*)&a3;
            float dot = ((f0.x + f0.y) + (f1.x + f1.y))
                      + ((f2.x + f2.y) + (f3.x + f3.y));
            float score = sN[k] - 2.f * dot;
            if (score < best) { best = score; bestk = k0 + k; }
        }
    }
    g_qidx[n] = bestk;
}

// ---------------- gather + transpose + reductions ----------------
// CTA: 256 threads, tile = 128 t for one batch b.
__global__ __launch_bounds__(256) void k_out(const float* __restrict__ embed,
                                             float* __restrict__ out) {
    __shared__ float zq[128][65];   // padded: conflict-free transposed reads
    __shared__ float red[8];

    int b  = blockIdx.x >> 5;
    int t0 = (blockIdx.x & 31) * 128;
    int tid = threadIdx.x;
    int tl   = tid >> 1;            // local t 0..127
    int half = tid & 1;             // which 32 of the 64 e's
    int n = b * TT + t0 + tl;
    int q = g_qidx[n];

    float lsum = 0.f;
    const float4* ep = (const float4*)(embed + (size_t)q * EE + half * 32);
    const float4* hp = (const float4*)(g_h + (size_t)n * EE + half * 32);
#pragma unroll
    for (int j = 0; j < 8; ++j) {
        float4 z = ep[j];
        float4 hh = hp[j];
        float dx = z.x - hh.x, dy = z.y - hh.y, dz = z.z - hh.z, dw = z.w - hh.w;
        lsum += dx * dx + dy * dy + dz * dz + dw * dw;
        int e = half * 32 + j * 4;
        zq[tl][e + 0] = z.x; zq[tl][e + 1] = z.y;
        zq[tl][e + 2] = z.z; zq[tl][e + 3] = z.w;
    }
    if (half == 0) atomicAdd(&g_counts[q], 1);   // int atomics: deterministic

    // warp + block reduce the commitment partial
#pragma unroll
    for (int s = 16; s > 0; s >>= 1) lsum += __shfl_down_sync(0xffffffffu, lsum, s);
    if ((tid & 31) == 0) red[tid >> 5] = lsum;
    __syncthreads();
    if (tid == 0) {
        float s = 0.f;
#pragma unroll
        for (int i = 0; i < 8; ++i) s += red[i];
        g_partials[blockIdx.x] = s;
    }

    // transposed write: out[b][e][t]
#pragma unroll
    for (int p = 0; p < 32; ++p) {
        int idx = p * 256 + tid;    // 0..8191
        int e = idx >> 7;
        int t = idx & 127;
        out[((size_t)b * EE + e) * TT + t0 + t] = zq[t][e];
    }
}

// ---------------- finalize scalars ----------------
__global__ void k_fin(float* __restrict__ out, int out_size) {
    __shared__ double sd[256];
    int tid = threadIdx.x;

    double lp = 0.0;
    for (int k = tid; k < KK; k += 256) {
        float p = (float)g_counts[k] / (float)NPTS;
        lp -= (double)(p * logf(p + 1e-10f));
    }
    sd[tid] = lp;
    __syncthreads();
    for (int s = 128; s > 0; s >>= 1) {
        if (tid < s) sd[tid] += sd[tid + s];
        __syncthreads();
    }

    if (out_size >= ZLEN + 18) {
        if (tid == 0) {
            out[ZLEN + 17] = (float)sd[0];
            double ds = 0.0;
            for (int i = 0; i < 512; ++i) ds += (double)g_partials[i];
            out[ZLEN] = (float)(0.25 * ds / ((double)NPTS * (double)EE));
        }
        if (tid >= 32 && tid < 48)
            out[ZLEN + 1 + (tid - 32)] = (float)(log(2048.0) * 4096.0);
    }
}

// ---------------- launch ----------------
extern "C" void kernel_launch(void* const* d_in, const int* in_sizes, int n_in,
                              void* d_out, int out_size) {
    const float* x  = (const float*)d_in[0];   // [B, CIN, T]
    const float* w  = (const float*)d_in[1];   // [E, CIN]
    const float* pb = (const float*)d_in[2];   // [E]
    const float* em = (const float*)d_in[3];   // [K, E]
    float* out = (float*)d_out;

    k_init<<<(KK + 255) / 256, 256>>>(em);
    k_proj<<<BB * (TT / TILE_T), 256>>>(x, w, pb);
    k_dist<<<NPTS / 128, 128>>>(em);
    k_out<<<BB * (TT / 128), 256>>>(em, out);
    k_fin<<<1, 256>>>(out, out_size);
}

// round 4
// speedup vs baseline: 1.4325x; 1.3819x over previous
#include <cuda_runtime.h>
#include <math.h>
#include <stdint.h>

#define BB   16
#define CIN  512
#define TT   4096
#define EE   64
#define KK   2048
#define NPTS (BB * TT)        // 65536
#define ZLEN (NPTS * EE)      // 4194304

typedef unsigned long long u64;

#define FMA2(d, a, b, c) \
    asm("fma.rn.f32x2 %0, %1, %2, %3;" : "=l"(d) : "l"(a), "l"(b), "l"(c))
#define BCAST2(d, s) \
    asm("mov.b64 %0, {%1, %1};" : "=l"(d) : "f"(s))

// tf32 split: v = hi + lo, both tf32-representable (stored as fp32 bits)
__device__ __forceinline__ void tf32split(float v, uint32_t& hi, uint32_t& lo) {
    asm("cvt.rna.tf32.f32 %0, %1;" : "=r"(hi) : "f"(v));
    float r = v - __uint_as_float(hi);
    asm("cvt.rna.tf32.f32 %0, %1;" : "=r"(lo) : "f"(r));
}

#define MMA168(c0, c1, c2, c3, a0, a1, a2, a3, b0, b1)                        \
    asm("mma.sync.aligned.m16n8k8.row.col.f32.tf32.tf32.f32 "                 \
        "{%0,%1,%2,%3}, {%4,%5,%6,%7}, {%8,%9}, {%0,%1,%2,%3};"               \
        : "+f"(c0), "+f"(c1), "+f"(c2), "+f"(c3)                              \
        : "r"(a0), "r"(a1), "r"(a2), "r"(a3), "r"(b0), "r"(b1))

// ---------------- device scratch ----------------
__device__ float g_h[ZLEN];          // projected features h[n][e]
__device__ float g_enorm[KK];        // ||e_k||^2
__device__ int   g_qidx[NPTS];       // argmin codeword per point
__device__ int   g_counts[KK];       // histogram
__device__ float g_partials[512];    // per-CTA commitment partial sums

// ---------------- init: codeword norms + zero counts ----------------
__global__ void k_init(const float* __restrict__ embed) {
    int k = blockIdx.x * blockDim.x + threadIdx.x;
    if (k < KK) {
        const float4* row = (const float4*)(embed + (size_t)k * EE);
        float s = 0.f;
#pragma unroll
        for (int j = 0; j < 16; ++j) {
            float4 v = row[j];
            s += v.x * v.x + v.y * v.y + v.z * v.z + v.w * v.w;
        }
        g_enorm[k] = s;
        g_counts[k] = 0;
    }
}

// ---------------- projection GEMM: h = w @ x + b ----------------
#define TILE_T 128
#define TILE_C 32

__global__ __launch_bounds__(256) void k_proj(const float* __restrict__ x,
                                              const float* __restrict__ w,
                                              const float* __restrict__ pb) {
    __shared__ float ws[TILE_C][68];
    __shared__ float xs[TILE_C][TILE_T];

    int b  = blockIdx.x >> 5;
    int t0 = (blockIdx.x & 31) * TILE_T;
    int tid = threadIdx.x;
    int te = tid & 15;
    int tt = tid >> 4;

    u64 acc2[8][2];
#pragma unroll
    for (int i = 0; i < 8; ++i) { acc2[i][0] = 0ull; acc2[i][1] = 0ull; }

    const float* xb = x + (size_t)b * CIN * TT + t0;

    for (int c0 = 0; c0 < CIN; c0 += TILE_C) {
#pragma unroll
        for (int p = 0; p < 2; ++p) {
            int idx = tid + p * 256;
            int e   = idx >> 3;
            int f4  = idx & 7;
            float4 v = *(const float4*)(w + (size_t)e * CIN + c0 + f4 * 4);
            ws[f4 * 4 + 0][e] = v.x;
            ws[f4 * 4 + 1][e] = v.y;
            ws[f4 * 4 + 2][e] = v.z;
            ws[f4 * 4 + 3][e] = v.w;
        }
#pragma unroll
        for (int p = 0; p < 4; ++p) {
            int idx = tid + p * 256;
            int c   = idx >> 5;
            int f4  = idx & 31;
            *(float4*)&xs[c][f4 * 4] =
                *(const float4*)(xb + (size_t)(c0 + c) * TT + f4 * 4);
        }
        __syncthreads();
#pragma unroll
        for (int c = 0; c < TILE_C; ++c) {
            float4 wv = *(const float4*)&ws[c][te * 4];
            u64 wlo = *(u64*)&wv.x;
            u64 whi = *(u64*)&wv.z;
#pragma unroll
            for (int i = 0; i < 8; ++i) {
                float xv = xs[c][tt + i * 16];
                u64 xx;
                BCAST2(xx, xv);
                FMA2(acc2[i][0], xx, wlo, acc2[i][0]);
                FMA2(acc2[i][1], xx, whi, acc2[i][1]);
            }
        }
        __syncthreads();
    }

    float4 bv = *(const float4*)(pb + te * 4);
#pragma unroll
    for (int i = 0; i < 8; ++i) {
        int t = t0 + tt + i * 16;
        float2 lo = *(float2*)&acc2[i][0];
        float2 hi = *(float2*)&acc2[i][1];
        float4 o;
        o.x = lo.x + bv.x;
        o.y = lo.y + bv.y;
        o.z = hi.x + bv.z;
        o.w = hi.y + bv.w;
        *(float4*)(g_h + ((size_t)b * TT + t) * EE + te * 4) = o;
    }
}

// ---------------- distance argmin via 3xTF32 tensor-core MMA ----------------
// CTA = 256 threads = 8 warps, 128 points/CTA (16 points per warp).
// Per warp: A fragments (h splits, 8 ksteps x 4 regs, hi+lo) live in regs for
// the whole kernel. Codebook staged in smem in 64-codeword chunks, tf32-split
// at staging. Score = ||e||^2 - 2*(Hh*Eh + Hh*El + Hl*Eh).
#define DKC 64

__global__ __launch_bounds__(256) void k_dist(const float* __restrict__ embed) {
    __shared__ float sEh[DKC][68];   // 17.4 KB
    __shared__ float sEl[DKC][68];   // 17.4 KB
    __shared__ float sN[DKC];

    int tid  = threadIdx.x;
    int wid  = tid >> 5;
    int lane = tid & 31;
    int g = lane >> 2;               // groupID 0..7
    int q = lane & 3;                // threadID in group 0..3

    int rowA = blockIdx.x * 128 + wid * 16 + g;   // point row (m = g)
    int rowB = rowA + 8;                          // point row (m = g+8)

    // ---- load A fragments once: m16k8 tf32 layout, hi+lo splits ----
    uint32_t Ah[8][4], Al[8][4];
#pragma unroll
    for (int s = 0; s < 8; ++s) {
        float v0 = g_h[(size_t)rowA * EE + s * 8 + q];
        float v1 = g_h[(size_t)rowB * EE + s * 8 + q];
        float v2 = g_h[(size_t)rowA * EE + s * 8 + q + 4];
        float v3 = g_h[(size_t)rowB * EE + s * 8 + q + 4];
        tf32split(v0, Ah[s][0], Al[s][0]);
        tf32split(v1, Ah[s][1], Al[s][1]);
        tf32split(v2, Ah[s][2], Al[s][2]);
        tf32split(v3, Ah[s][3], Al[s][3]);
    }

    float bestA = 3.4e38f, bestB = 3.4e38f;
    int   bkA = 0, bkB = 0;

    for (int k0 = 0; k0 < KK; k0 += DKC) {
        __syncthreads();
        // stage + split the codebook chunk
        for (int i = tid; i < DKC * EE; i += 256) {
            int r = i >> 6;
            int c = i & 63;
            float v = embed[(size_t)(k0 + r) * EE + c];
            uint32_t hi, lo;
            tf32split(v, hi, lo);
            sEh[r][c] = __uint_as_float(hi);
            sEl[r][c] = __uint_as_float(lo);
        }
        if (tid < DKC) sN[tid] = g_enorm[k0 + tid];
        __syncthreads();

        for (int nb = 0; nb < DKC; nb += 8) {
            float c0 = 0.f, c1 = 0.f, c2 = 0.f, c3 = 0.f;
#pragma unroll
            for (int s = 0; s < 8; ++s) {
                // B k8n8 col-major: b0 = E[n=g][k=s*8+q], b1 = k+4
                uint32_t beh0 = __float_as_uint(sEh[nb + g][s * 8 + q]);
                uint32_t beh1 = __float_as_uint(sEh[nb + g][s * 8 + q + 4]);
                uint32_t bel0 = __float_as_uint(sEl[nb + g][s * 8 + q]);
                uint32_t bel1 = __float_as_uint(sEl[nb + g][s * 8 + q + 4]);
                MMA168(c0, c1, c2, c3, Ah[s][0], Ah[s][1], Ah[s][2], Ah[s][3], beh0, beh1);
                MMA168(c0, c1, c2, c3, Ah[s][0], Ah[s][1], Ah[s][2], Ah[s][3], bel0, bel1);
                MMA168(c0, c1, c2, c3, Al[s][0], Al[s][1], Al[s][2], Al[s][3], beh0, beh1);
            }
            // C m16n8: c0=(g, 2q) c1=(g, 2q+1) c2=(g+8, 2q) c3=(g+8, 2q+1)
            int kb = k0 + nb;
            float sn0 = sN[nb + 2 * q];
            float sn1 = sN[nb + 2 * q + 1];
            float s0 = sn0 - 2.f * c0;
            float s1 = sn1 - 2.f * c1;
            float s2 = sn0 - 2.f * c2;
            float s3 = sn1 - 2.f * c3;
            if (s0 < bestA) { bestA = s0; bkA = kb + 2 * q; }
            if (s1 < bestA) { bestA = s1; bkA = kb + 2 * q + 1; }
            if (s2 < bestB) { bestB = s2; bkB = kb + 2 * q; }
            if (s3 < bestB) { bestB = s3; bkB = kb + 2 * q + 1; }
        }
    }

    // quad reduce (lanes differing in low 2 bits hold same rows, diff cols)
#pragma unroll
    for (int off = 1; off <= 2; off <<= 1) {
        float oA = __shfl_xor_sync(0xffffffffu, bestA, off);
        int   kA = __shfl_xor_sync(0xffffffffu, bkA, off);
        float oB = __shfl_xor_sync(0xffffffffu, bestB, off);
        int   kB = __shfl_xor_sync(0xffffffffu, bkB, off);
        if (oA < bestA || (oA == bestA && kA < bkA)) { bestA = oA; bkA = kA; }
        if (oB < bestB || (oB == bestB && kB < bkB)) { bestB = oB; bkB = kB; }
    }
    if (q == 0) {
        g_qidx[rowA] = bkA;
        g_qidx[rowB] = bkB;
    }
}

// ---------------- gather + transpose + reductions ----------------
__global__ __launch_bounds__(256) void k_out(const float* __restrict__ embed,
                                             float* __restrict__ out) {
    __shared__ float zq[128][65];
    __shared__ float red[8];

    int b  = blockIdx.x >> 5;
    int t0 = (blockIdx.x & 31) * 128;
    int tid = threadIdx.x;
    int tl   = tid >> 1;
    int half = tid & 1;
    int n = b * TT + t0 + tl;
    int q = g_qidx[n];

    float lsum = 0.f;
    const float4* ep = (const float4*)(embed + (size_t)q * EE + half * 32);
    const float4* hp = (const float4*)(g_h + (size_t)n * EE + half * 32);
#pragma unroll
    for (int j = 0; j < 8; ++j) {
        float4 z = ep[j];
        float4 hh = hp[j];
        float dx = z.x - hh.x, dy = z.y - hh.y, dz = z.z - hh.z, dw = z.w - hh.w;
        lsum += dx * dx + dy * dy + dz * dz + dw * dw;
        int e = half * 32 + j * 4;
        zq[tl][e + 0] = z.x; zq[tl][e + 1] = z.y;
        zq[tl][e + 2] = z.z; zq[tl][e + 3] = z.w;
    }
    if (half == 0) atomicAdd(&g_counts[q], 1);

#pragma unroll
    for (int s = 16; s > 0; s >>= 1) lsum += __shfl_down_sync(0xffffffffu, lsum, s);
    if ((tid & 31) == 0) red[tid >> 5] = lsum;
    __syncthreads();
    if (tid == 0) {
        float s = 0.f;
#pragma unroll
        for (int i = 0; i < 8; ++i) s += red[i];
        g_partials[blockIdx.x] = s;
    }

#pragma unroll
    for (int p = 0; p < 32; ++p) {
        int idx = p * 256 + tid;
        int e = idx >> 7;
        int t = idx & 127;
        out[((size_t)b * EE + e) * TT + t0 + t] = zq[t][e];
    }
}

// ---------------- finalize scalars ----------------
__global__ void k_fin(float* __restrict__ out, int out_size) {
    __shared__ double sd[256];
    int tid = threadIdx.x;

    double lp = 0.0;
    for (int k = tid; k < KK; k += 256) {
        float p = (float)g_counts[k] / (float)NPTS;
        lp -= (double)(p * logf(p + 1e-10f));
    }
    sd[tid] = lp;
    __syncthreads();
    for (int s = 128; s > 0; s >>= 1) {
        if (tid < s) sd[tid] += sd[tid + s];
        __syncthreads();
    }

    if (out_size >= ZLEN + 18) {
        if (tid == 0) {
            out[ZLEN + 17] = (float)sd[0];
            double ds = 0.0;
            for (int i = 0; i < 512; ++i) ds += (double)g_partials[i];
            out[ZLEN] = (float)(0.25 * ds / ((double)NPTS * (double)EE));
        }
        if (tid >= 32 && tid < 48)
            out[ZLEN + 1 + (tid - 32)] = (float)(log(2048.0) * 4096.0);
    }
}

// ---------------- launch ----------------
extern "C" void kernel_launch(void* const* d_in, const int* in_sizes, int n_in,
                              void* d_out, int out_size) {
    const float* x  = (const float*)d_in[0];   // [B, CIN, T]
    const float* w  = (const float*)d_in[1];   // [E, CIN]
    const float* pb = (const float*)d_in[2];   // [E]
    const float* em = (const float*)d_in[3];   // [K, E]
    float* out = (float*)d_out;

    k_init<<<(KK + 255) / 256, 256>>>(em);
    k_proj<<<BB * (TT / TILE_T), 256>>>(x, w, pb);
    k_dist<<<NPTS / 128, 256>>>(em);
    k_out<<<BB * (TT / 128), 256>>>(em, out);
    k_fin<<<1, 256>>>(out, out_size);
}

// round 6
// speedup vs baseline: 2.2157x; 1.5467x over previous
#include <cuda_runtime.h>
#include <cuda_fp16.h>
#include <math.h>
#include <stdint.h>

#define BB   16
#define CIN  512
#define TT   4096
#define EE   64
#define KK   2048
#define NPTS (BB * TT)        // 65536
#define ZLEN (NPTS * EE)      // 4194304

typedef unsigned long long u64;

#define FMA2(d, a, b, c) \
    asm("fma.rn.f32x2 %0, %1, %2, %3;" : "=l"(d) : "l"(a), "l"(b), "l"(c))
#define BCAST2(d, s) \
    asm("mov.b64 %0, {%1, %1};" : "=l"(d) : "f"(s))

// fp16 split of a float2: v = hi + lo elementwise, packed as half2 (u32 bits)
__device__ __forceinline__ void f16s(float2 v, uint32_t& hi, uint32_t& lo) {
    __half2 h = __floats2half2_rn(v.x, v.y);
    float2 hf = __half22float2(h);
    __half2 l = __floats2half2_rn(v.x - hf.x, v.y - hf.y);
    hi = *(uint32_t*)&h;
    lo = *(uint32_t*)&l;
}

// m16n8k16 fp16 MMA, fp32 accumulate
#define MMAF16(c0, c1, c2, c3, a0, a1, a2, a3, b0, b1)                        \
    asm("mma.sync.aligned.m16n8k16.row.col.f32.f16.f16.f32 "                  \
        "{%0,%1,%2,%3}, {%4,%5,%6,%7}, {%8,%9}, {%0,%1,%2,%3};"               \
        : "+f"(c0), "+f"(c1), "+f"(c2), "+f"(c3)                              \
        : "r"(a0), "r"(a1), "r"(a2), "r"(a3), "r"(b0), "r"(b1))

// ---------------- device scratch ----------------
__device__ float g_h[ZLEN];          // projected features h[n][e]
__device__ float g_enorm[KK];        // ||e_k||^2
__device__ int   g_qidx[NPTS];       // argmin codeword per point
__device__ int   g_counts[KK];       // histogram
__device__ float g_partials[512];    // per-CTA commitment partials

// ---------------- init: codeword norms + zero counts ----------------
__global__ void k_init(const float* __restrict__ embed) {
    int k = blockIdx.x * blockDim.x + threadIdx.x;
    if (k < KK) {
        const float4* row = (const float4*)(embed + (size_t)k * EE);
        float s = 0.f;
#pragma unroll
        for (int j = 0; j < 16; ++j) {
            float4 v = row[j];
            s += v.x * v.x + v.y * v.y + v.z * v.z + v.w * v.w;
        }
        g_enorm[k] = s;
        g_counts[k] = 0;
    }
}

// ---------------- projection GEMM: h = w @ x + b (fp32, unchanged) -------
#define TILE_T 128
#define TILE_C 32

__global__ __launch_bounds__(256) void k_proj(const float* __restrict__ x,
                                              const float* __restrict__ w,
                                              const float* __restrict__ pb) {
    __shared__ float ws[TILE_C][68];
    __shared__ float xs[TILE_C][TILE_T];

    int b  = blockIdx.x >> 5;
    int t0 = (blockIdx.x & 31) * TILE_T;
    int tid = threadIdx.x;
    int te = tid & 15;
    int tt = tid >> 4;

    u64 acc2[8][2];
#pragma unroll
    for (int i = 0; i < 8; ++i) { acc2[i][0] = 0ull; acc2[i][1] = 0ull; }

    const float* xb = x + (size_t)b * CIN * TT + t0;

    for (int c0 = 0; c0 < CIN; c0 += TILE_C) {
#pragma unroll
        for (int p = 0; p < 2; ++p) {
            int idx = tid + p * 256;
            int e   = idx >> 3;
            int f4  = idx & 7;
            float4 v = *(const float4*)(w + (size_t)e * CIN + c0 + f4 * 4);
            ws[f4 * 4 + 0][e] = v.x;
            ws[f4 * 4 + 1][e] = v.y;
            ws[f4 * 4 + 2][e] = v.z;
            ws[f4 * 4 + 3][e] = v.w;
        }
#pragma unroll
        for (int p = 0; p < 4; ++p) {
            int idx = tid + p * 256;
            int c   = idx >> 5;
            int f4  = idx & 31;
            *(float4*)&xs[c][f4 * 4] =
                *(const float4*)(xb + (size_t)(c0 + c) * TT + f4 * 4);
        }
        __syncthreads();
#pragma unroll
        for (int c = 0; c < TILE_C; ++c) {
            float4 wv = *(const float4*)&ws[c][te * 4];
            u64 wlo = *(u64*)&wv.x;
            u64 whi = *(u64*)&wv.z;
#pragma unroll
            for (int i = 0; i < 8; ++i) {
                float xv = xs[c][tt + i * 16];
                u64 xx;
                BCAST2(xx, xv);
                FMA2(acc2[i][0], xx, wlo, acc2[i][0]);
                FMA2(acc2[i][1], xx, whi, acc2[i][1]);
            }
        }
        __syncthreads();
    }

    float4 bv = *(const float4*)(pb + te * 4);
#pragma unroll
    for (int i = 0; i < 8; ++i) {
        int t = t0 + tt + i * 16;
        float2 lo = *(float2*)&acc2[i][0];
        float2 hi = *(float2*)&acc2[i][1];
        float4 o;
        o.x = lo.x + bv.x;
        o.y = lo.y + bv.y;
        o.z = hi.x + bv.z;
        o.w = hi.y + bv.w;
        *(float4*)(g_h + ((size_t)b * TT + t) * EE + te * 4) = o;
    }
}

// ---------------- distance argmin via fp16 3-split mma.sync ----------------
// CTA = 256 threads = 8 warps, 128 points (16/warp). Codebook in 64-codeword
// chunks; B fragments pre-packed in smem as u64 {b0,b1}, row stride 160B
// (conflict-free LDS.64). Score = ||e||^2 - 2*(Hh*Eh + Hh*El + Hl*Eh).
#define DKC 64

__global__ __launch_bounds__(256) void k_dist(const float* __restrict__ embed) {
    __shared__ __align__(16) unsigned char sBh[DKC * 160];  // 10 KB
    __shared__ __align__(16) unsigned char sBl[DKC * 160];  // 10 KB
    __shared__ float sN[DKC];

    int tid  = threadIdx.x;
    int wid  = tid >> 5;
    int lane = tid & 31;
    int g = lane >> 2;               // 0..7
    int q = lane & 3;                // 0..3

    int rowA = blockIdx.x * 128 + wid * 16 + g;
    int rowB = rowA + 8;

    // A fragments: m16n8k16 layout, hi+lo splits. 4 ksteps cover k=64.
    uint32_t Ah[4][4], Al[4][4];
#pragma unroll
    for (int s = 0; s < 4; ++s) {
        const float* pA = g_h + (size_t)rowA * EE + s * 16 + 2 * q;
        const float* pB = g_h + (size_t)rowB * EE + s * 16 + 2 * q;
        f16s(*(const float2*)pA,       Ah[s][0], Al[s][0]);
        f16s(*(const float2*)pB,       Ah[s][1], Al[s][1]);
        f16s(*(const float2*)(pA + 8), Ah[s][2], Al[s][2]);
        f16s(*(const float2*)(pB + 8), Ah[s][3], Al[s][3]);
    }

    float bestA = 3.4e38f, bestB = 3.4e38f;
    int   bkA = 0, bkB = 0;

    for (int c = 0; c < KK / DKC; ++c) {
        __syncthreads();
        // stage chunk: split to fp16 hi/lo, pre-pack mma B fragment slots
        const float* src = embed + (size_t)c * DKC * EE;
#pragma unroll
        for (int p = 0; p < 8; ++p) {
            int i = tid + p * 256;       // 0..2047
            int n = i >> 5;              // codeword row in chunk
            int l = i & 31;              // k-pair index (k = 2l)
            float2 v = *(const float2*)(src + (size_t)n * EE + 2 * l);
            uint32_t hi, lo;
            f16s(v, hi, lo);
            uint32_t off = (uint32_t)(n * 160 + (((l >> 3) * 4 + (l & 3)) << 3)
                                      + (((l >> 2) & 1) << 2));
            *(uint32_t*)(sBh + off) = hi;
            *(uint32_t*)(sBl + off) = lo;
        }
        if (tid < DKC) sN[tid] = g_enorm[c * DKC + tid];
        __syncthreads();

        for (int nb = 0; nb < DKC; nb += 8) {
            float c0 = 0.f, c1 = 0.f, c2 = 0.f, c3 = 0.f;
            uint32_t boff = (uint32_t)((nb + g) * 160 + q * 8);
#pragma unroll
            for (int s = 0; s < 4; ++s) {
                uint2 bh = *(const uint2*)(sBh + boff + s * 32);
                uint2 bl = *(const uint2*)(sBl + boff + s * 32);
                MMAF16(c0, c1, c2, c3,
                       Ah[s][0], Ah[s][1], Ah[s][2], Ah[s][3], bh.x, bh.y);
                MMAF16(c0, c1, c2, c3,
                       Ah[s][0], Ah[s][1], Ah[s][2], Ah[s][3], bl.x, bl.y);
                MMAF16(c0, c1, c2, c3,
                       Al[s][0], Al[s][1], Al[s][2], Al[s][3], bh.x, bh.y);
            }
            // C m16n8: c0=(g,2q) c1=(g,2q+1) c2=(g+8,2q) c3=(g+8,2q+1)
            int kb = c * DKC + nb;
            float sn0 = sN[nb + 2 * q];
            float sn1 = sN[nb + 2 * q + 1];
            float s0 = sn0 - 2.f * c0;
            float s1 = sn1 - 2.f * c1;
            float s2 = sn0 - 2.f * c2;
            float s3 = sn1 - 2.f * c3;
            if (s0 < bestA) { bestA = s0; bkA = kb + 2 * q; }
            if (s1 < bestA) { bestA = s1; bkA = kb + 2 * q + 1; }
            if (s2 < bestB) { bestB = s2; bkB = kb + 2 * q; }
            if (s3 < bestB) { bestB = s3; bkB = kb + 2 * q + 1; }
        }
    }

    // quad reduce (lanes differing in low 2 bits: same rows, different cols)
#pragma unroll
    for (int off = 1; off <= 2; off <<= 1) {
        float oA = __shfl_xor_sync(0xffffffffu, bestA, off);
        int   kA = __shfl_xor_sync(0xffffffffu, bkA, off);
        float oB = __shfl_xor_sync(0xffffffffu, bestB, off);
        int   kB = __shfl_xor_sync(0xffffffffu, bkB, off);
        if (oA < bestA || (oA == bestA && kA < bkA)) { bestA = oA; bkA = kA; }
        if (oB < bestB || (oB == bestB && kB < bkB)) { bestB = oB; bkB = kB; }
    }
    if (q == 0) {
        g_qidx[rowA] = bkA;
        g_qidx[rowB] = bkB;
    }
}

// ---------------- gather + transpose + reductions ----------------
__global__ __launch_bounds__(256) void k_out(const float* __restrict__ embed,
                                             float* __restrict__ out) {
    __shared__ float zq[128][65];
    __shared__ float red[8];

    int b  = blockIdx.x >> 5;
    int t0 = (blockIdx.x & 31) * 128;
    int tid = threadIdx.x;
    int tl   = tid >> 1;
    int half = tid & 1;
    int n = b * TT + t0 + tl;
    int q = g_qidx[n];

    float lsum = 0.f;
    const float4* ep = (const float4*)(embed + (size_t)q * EE + half * 32);
    const float4* hp = (const float4*)(g_h + (size_t)n * EE + half * 32);
#pragma unroll
    for (int j = 0; j < 8; ++j) {
        float4 z = ep[j];
        float4 hh = hp[j];
        float dx = z.x - hh.x, dy = z.y - hh.y, dz = z.z - hh.z, dw = z.w - hh.w;
        lsum += dx * dx + dy * dy + dz * dz + dw * dw;
        int e = half * 32 + j * 4;
        zq[tl][e + 0] = z.x; zq[tl][e + 1] = z.y;
        zq[tl][e + 2] = z.z; zq[tl][e + 3] = z.w;
    }
    if (half == 0) atomicAdd(&g_counts[q], 1);

#pragma unroll
    for (int s = 16; s > 0; s >>= 1) lsum += __shfl_down_sync(0xffffffffu, lsum, s);
    if ((tid & 31) == 0) red[tid >> 5] = lsum;
    __syncthreads();
    if (tid == 0) {
        float s = 0.f;
#pragma unroll
        for (int i = 0; i < 8; ++i) s += red[i];
        g_partials[blockIdx.x] = s;
    }

#pragma unroll
    for (int p = 0; p < 32; ++p) {
        int idx = p * 256 + tid;
        int e = idx >> 7;
        int t = idx & 127;
        out[((size_t)b * EE + e) * TT + t0 + t] = zq[t][e];
    }
}

// ---------------- finalize scalars ----------------
__global__ void k_fin(float* __restrict__ out, int out_size) {
    __shared__ double sd[256];
    int tid = threadIdx.x;

    double lp = 0.0;
    for (int k = tid; k < KK; k += 256) {
        float p = (float)g_counts[k] / (float)NPTS;
        lp -= (double)(p * logf(p + 1e-10f));
    }
    sd[tid] = lp;
    __syncthreads();
    for (int s = 128; s > 0; s >>= 1) {
        if (tid < s) sd[tid] += sd[tid + s];
        __syncthreads();
    }

    if (out_size >= ZLEN + 18) {
        if (tid == 0) {
            out[ZLEN + 17] = (float)sd[0];
            double ds = 0.0;
            for (int i = 0; i < 512; ++i) ds += (double)g_partials[i];
            out[ZLEN] = (float)(0.25 * ds / ((double)NPTS * (double)EE));
        }
        if (tid >= 32 && tid < 48)
            out[ZLEN + 1 + (tid - 32)] = (float)(log(2048.0) * 4096.0);
    }
}

// ---------------- launch ----------------
extern "C" void kernel_launch(void* const* d_in, const int* in_sizes, int n_in,
                              void* d_out, int out_size) {
    const float* x  = (const float*)d_in[0];   // [B, CIN, T]
    const float* w  = (const float*)d_in[1];   // [E, CIN]
    const float* pb = (const float*)d_in[2];   // [E]
    const float* em = (const float*)d_in[3];   // [K, E]
    float* out = (float*)d_out;

    k_init<<<(KK + 255) / 256, 256>>>(em);
    k_proj<<<BB * (TT / TILE_T), 256>>>(x, w, pb);
    k_dist<<<NPTS / 128, 256>>>(em);
    k_out<<<BB * (TT / 128), 256>>>(em, out);
    k_fin<<<1, 256>>>(out, out_size);
}

// round 7
// speedup vs baseline: 2.7459x; 1.2393x over previous
#include <cuda_runtime.h>
#include <cuda_fp16.h>
#include <math.h>
#include <stdint.h>

#define BB   16
#define CIN  512
#define TT   4096
#define EE   64
#define KK   2048
#define NPTS (BB * TT)        // 65536
#define ZLEN (NPTS * EE)      // 4194304

typedef unsigned long long u64;

// fp16 split of a float2: v = hi + lo elementwise, packed as half2 (u32 bits)
__device__ __forceinline__ void f16s(float2 v, uint32_t& hi, uint32_t& lo) {
    __half2 h = __floats2half2_rn(v.x, v.y);
    float2 hf = __half22float2(h);
    __half2 l = __floats2half2_rn(v.x - hf.x, v.y - hf.y);
    hi = *(uint32_t*)&h;
    lo = *(uint32_t*)&l;
}

// m16n8k16 fp16 MMA, fp32 accumulate
#define MMAF16(c0, c1, c2, c3, a0, a1, a2, a3, b0, b1)                        \
    asm("mma.sync.aligned.m16n8k16.row.col.f32.f16.f16.f32 "                  \
        "{%0,%1,%2,%3}, {%4,%5,%6,%7}, {%8,%9}, {%0,%1,%2,%3};"               \
        : "+f"(c0), "+f"(c1), "+f"(c2), "+f"(c3)                              \
        : "r"(a0), "r"(a1), "r"(a2), "r"(a3), "r"(b0), "r"(b1))

// packed-fragment slot (bytes within a 160B row) for k-pair index l (k=2l)
__device__ __forceinline__ uint32_t fslot(int l) {
    return (uint32_t)((((l >> 3) * 4 + (l & 3)) << 3) + (((l >> 2) & 1) << 2));
}

// ---------------- device scratch ----------------
__device__ float    g_h[ZLEN];        // projected features h[n][e]
__device__ float    g_enorm[KK];      // ||e_k||^2
__device__ int      g_qidx[NPTS];     // argmin codeword per point
__device__ int      g_counts[KK];     // histogram
__device__ float    g_partials[512];  // per-CTA commitment partials
__device__ uint32_t g_wfh[8 * 64 * 40];  // w fragments hi (8 chunks x 64e x 160B)
__device__ uint32_t g_wfl[8 * 64 * 40];  // w fragments lo

// ---------------- init: codeword norms + zero counts ----------------
__global__ void k_init(const float* __restrict__ embed) {
    int k = blockIdx.x * blockDim.x + threadIdx.x;
    if (k < KK) {
        const float4* row = (const float4*)(embed + (size_t)k * EE);
        float s = 0.f;
#pragma unroll
        for (int j = 0; j < 16; ++j) {
            float4 v = row[j];
            s += v.x * v.x + v.y * v.y + v.z * v.z + v.w * v.w;
        }
        g_enorm[k] = s;
        g_counts[k] = 0;
    }
}

// ---------------- w fragment pre-split (runs once, trivial) ----------------
__global__ void k_wsplit(const float* __restrict__ w) {
    int i = blockIdx.x * 256 + threadIdx.x;     // 0..16383
    if (i >= 8 * 64 * 32) return;
    int ch = i >> 11;
    int e  = (i >> 5) & 63;
    int l  = i & 31;                            // k-pair within chunk
    float2 v = *(const float2*)(w + (size_t)e * CIN + ch * 64 + 2 * l);
    uint32_t hi, lo;
    f16s(v, hi, lo);
    uint32_t off = (uint32_t)(ch * 64 * 40 + e * 40) + (fslot(l) >> 2);
    g_wfh[off] = hi;
    g_wfl[off] = lo;
}

// ---------------- projection GEMM via fp16 3-split mma.sync ----------------
// CTA: 256 thr / 8 warps, output 128t x 64e. Warp w: rows 16w..16w+15, all e.
// K-chunks of 64: x staged fp32 (pad-132 rows, conflict-free transpose reads),
// w fragments copied pre-packed from global.
#define PXS   0
#define PBH   33792
#define PBL   44032
#define PTOT  54272

__global__ __launch_bounds__(256) void k_projmma(const float* __restrict__ x,
                                                 const float* __restrict__ pb) {
    extern __shared__ char sm[];
    float* xs = (float*)(sm + PXS);                 // [64][132]
    unsigned char* sBh = (unsigned char*)(sm + PBH);
    unsigned char* sBl = (unsigned char*)(sm + PBL);

    int tid  = threadIdx.x;
    int wid  = tid >> 5;
    int lane = tid & 31;
    int g = lane >> 2;
    int q = lane & 3;

    int b  = blockIdx.x >> 5;
    int t0 = (blockIdx.x & 31) * 128;
    const float* xb = x + (size_t)b * CIN * TT + t0;

    float acc[8][4];
#pragma unroll
    for (int nb = 0; nb < 8; ++nb)
#pragma unroll
        for (int j = 0; j < 4; ++j) acc[nb][j] = 0.f;

    int m0 = wid * 16 + g;

    for (int ch = 0; ch < 8; ++ch) {
        __syncthreads();
        // stage x chunk [64 c][128 t] (coalesced float4 along t)
#pragma unroll
        for (int p = 0; p < 8; ++p) {
            int idx = tid + p * 256;        // 0..2047
            int c = idx >> 5;
            int f = idx & 31;
            *(float4*)&xs[c * 132 + f * 4] =
                *(const float4*)(xb + (size_t)(ch * 64 + c) * TT + f * 4);
        }
        // copy pre-packed w fragments (640 uint4 each)
        {
            const uint4* wh = (const uint4*)(g_wfh + ch * 2560);
            const uint4* wl = (const uint4*)(g_wfl + ch * 2560);
#pragma unroll
            for (int p = 0; p < 3; ++p) {
                int i = tid + p * 256;
                if (i < 640) {
                    ((uint4*)sBh)[i] = wh[i];
                    ((uint4*)sBl)[i] = wl[i];
                }
            }
        }
        __syncthreads();

#pragma unroll
        for (int s = 0; s < 4; ++s) {
            int c = s * 16 + 2 * q;
            uint32_t a0h, a0l, a1h, a1l, a2h, a2l, a3h, a3l;
            f16s(make_float2(xs[c * 132 + m0],           xs[(c + 1) * 132 + m0]),           a0h, a0l);
            f16s(make_float2(xs[c * 132 + m0 + 8],       xs[(c + 1) * 132 + m0 + 8]),       a1h, a1l);
            f16s(make_float2(xs[(c + 8) * 132 + m0],     xs[(c + 9) * 132 + m0]),           a2h, a2l);
            f16s(make_float2(xs[(c + 8) * 132 + m0 + 8], xs[(c + 9) * 132 + m0 + 8]),       a3h, a3l);
#pragma unroll
            for (int nb = 0; nb < 8; ++nb) {
                uint32_t boff = (uint32_t)((nb * 8 + g) * 160 + q * 8 + s * 32);
                uint2 bh = *(const uint2*)(sBh + boff);
                uint2 bl = *(const uint2*)(sBl + boff);
                MMAF16(acc[nb][0], acc[nb][1], acc[nb][2], acc[nb][3],
                       a0h, a1h, a2h, a3h, bh.x, bh.y);
                MMAF16(acc[nb][0], acc[nb][1], acc[nb][2], acc[nb][3],
                       a0h, a1h, a2h, a3h, bl.x, bl.y);
                MMAF16(acc[nb][0], acc[nb][1], acc[nb][2], acc[nb][3],
                       a0l, a1l, a2l, a3l, bh.x, bh.y);
            }
        }
    }

    // epilogue: add bias, store (rows m0 and m0+8; cols nb*8+2q, +1)
#pragma unroll
    for (int nb = 0; nb < 8; ++nb) {
        float2 bv = *(const float2*)(pb + nb * 8 + 2 * q);
        float2 o0 = make_float2(acc[nb][0] + bv.x, acc[nb][1] + bv.y);
        float2 o1 = make_float2(acc[nb][2] + bv.x, acc[nb][3] + bv.y);
        size_t base = ((size_t)(b * TT + t0 + m0)) * EE + nb * 8 + 2 * q;
        *(float2*)(g_h + base) = o0;
        *(float2*)(g_h + base + 8 * EE) = o1;
    }
}

// ---------------- distance argmin via fp16 3-split mma.sync ----------------
#define DKC 64

__global__ __launch_bounds__(256) void k_dist(const float* __restrict__ embed) {
    __shared__ __align__(16) unsigned char sBh[DKC * 160];  // 10 KB
    __shared__ __align__(16) unsigned char sBl[DKC * 160];  // 10 KB
    __shared__ float sN[DKC];

    int tid  = threadIdx.x;
    int wid  = tid >> 5;
    int lane = tid & 31;
    int g = lane >> 2;
    int q = lane & 3;

    int rowA = blockIdx.x * 128 + wid * 16 + g;
    int rowB = rowA + 8;

    uint32_t Ah[4][4], Al[4][4];
#pragma unroll
    for (int s = 0; s < 4; ++s) {
        const float* pA = g_h + (size_t)rowA * EE + s * 16 + 2 * q;
        const float* pB = g_h + (size_t)rowB * EE + s * 16 + 2 * q;
        f16s(*(const float2*)pA,       Ah[s][0], Al[s][0]);
        f16s(*(const float2*)pB,       Ah[s][1], Al[s][1]);
        f16s(*(const float2*)(pA + 8), Ah[s][2], Al[s][2]);
        f16s(*(const float2*)(pB + 8), Ah[s][3], Al[s][3]);
    }

    float bestA = 3.4e38f, bestB = 3.4e38f;
    int   bkA = 0, bkB = 0;

    for (int c = 0; c < KK / DKC; ++c) {
        __syncthreads();
        const float* src = embed + (size_t)c * DKC * EE;
#pragma unroll
        for (int p = 0; p < 8; ++p) {
            int i = tid + p * 256;
            int n = i >> 5;
            int l = i & 31;
            float2 v = *(const float2*)(src + (size_t)n * EE + 2 * l);
            uint32_t hi, lo;
            f16s(v, hi, lo);
            uint32_t off = (uint32_t)(n * 160) + fslot(l);
            *(uint32_t*)(sBh + off) = hi;
            *(uint32_t*)(sBl + off) = lo;
        }
        if (tid < DKC) sN[tid] = g_enorm[c * DKC + tid];
        __syncthreads();

        for (int nb = 0; nb < DKC; nb += 8) {
            float c0 = 0.f, c1 = 0.f, c2 = 0.f, c3 = 0.f;
            uint32_t boff = (uint32_t)((nb + g) * 160 + q * 8);
#pragma unroll
            for (int s = 0; s < 4; ++s) {
                uint2 bh = *(const uint2*)(sBh + boff + s * 32);
                uint2 bl = *(const uint2*)(sBl + boff + s * 32);
                MMAF16(c0, c1, c2, c3,
                       Ah[s][0], Ah[s][1], Ah[s][2], Ah[s][3], bh.x, bh.y);
                MMAF16(c0, c1, c2, c3,
                       Ah[s][0], Ah[s][1], Ah[s][2], Ah[s][3], bl.x, bl.y);
                MMAF16(c0, c1, c2, c3,
                       Al[s][0], Al[s][1], Al[s][2], Al[s][3], bh.x, bh.y);
            }
            int kb = c * DKC + nb;
            float sn0 = sN[nb + 2 * q];
            float sn1 = sN[nb + 2 * q + 1];
            float s0 = sn0 - 2.f * c0;
            float s1 = sn1 - 2.f * c1;
            float s2 = sn0 - 2.f * c2;
            float s3 = sn1 - 2.f * c3;
            if (s0 < bestA) { bestA = s0; bkA = kb + 2 * q; }
            if (s1 < bestA) { bestA = s1; bkA = kb + 2 * q + 1; }
            if (s2 < bestB) { bestB = s2; bkB = kb + 2 * q; }
            if (s3 < bestB) { bestB = s3; bkB = kb + 2 * q + 1; }
        }
    }

#pragma unroll
    for (int off = 1; off <= 2; off <<= 1) {
        float oA = __shfl_xor_sync(0xffffffffu, bestA, off);
        int   kA = __shfl_xor_sync(0xffffffffu, bkA, off);
        float oB = __shfl_xor_sync(0xffffffffu, bestB, off);
        int   kB = __shfl_xor_sync(0xffffffffu, bkB, off);
        if (oA < bestA || (oA == bestA && kA < bkA)) { bestA = oA; bkA = kA; }
        if (oB < bestB || (oB == bestB && kB < bkB)) { bestB = oB; bkB = kB; }
    }
    if (q == 0) {
        g_qidx[rowA] = bkA;
        g_qidx[rowB] = bkB;
    }
}

// ---------------- gather + transpose + reductions ----------------
__global__ __launch_bounds__(256) void k_out(const float* __restrict__ embed,
                                             float* __restrict__ out) {
    __shared__ float zq[128][65];
    __shared__ float red[8];

    int b  = blockIdx.x >> 5;
    int t0 = (blockIdx.x & 31) * 128;
    int tid = threadIdx.x;
    int tl   = tid >> 1;
    int half = tid & 1;
    int n = b * TT + t0 + tl;
    int q = g_qidx[n];

    float lsum = 0.f;
    const float4* ep = (const float4*)(embed + (size_t)q * EE + half * 32);
    const float4* hp = (const float4*)(g_h + (size_t)n * EE + half * 32);
#pragma unroll
    for (int j = 0; j < 8; ++j) {
        float4 z = ep[j];
        float4 hh = hp[j];
        float dx = z.x - hh.x, dy = z.y - hh.y, dz = z.z - hh.z, dw = z.w - hh.w;
        lsum += dx * dx + dy * dy + dz * dz + dw * dw;
        int e = half * 32 + j * 4;
        zq[tl][e + 0] = z.x; zq[tl][e + 1] = z.y;
        zq[tl][e + 2] = z.z; zq[tl][e + 3] = z.w;
    }
    if (half == 0) atomicAdd(&g_counts[q], 1);

#pragma unroll
    for (int s = 16; s > 0; s >>= 1) lsum += __shfl_down_sync(0xffffffffu, lsum, s);
    if ((tid & 31) == 0) red[tid >> 5] = lsum;
    __syncthreads();
    if (tid == 0) {
        float s = 0.f;
#pragma unroll
        for (int i = 0; i < 8; ++i) s += red[i];
        g_partials[blockIdx.x] = s;
    }

#pragma unroll
    for (int p = 0; p < 32; ++p) {
        int idx = p * 256 + tid;
        int e = idx >> 7;
        int t = idx & 127;
        out[((size_t)b * EE + e) * TT + t0 + t] = zq[t][e];
    }
}

// ---------------- finalize scalars ----------------
__global__ void k_fin(float* __restrict__ out, int out_size) {
    __shared__ double sd[256];
    int tid = threadIdx.x;

    double lp = 0.0;
    for (int k = tid; k < KK; k += 256) {
        float p = (float)g_counts[k] / (float)NPTS;
        lp -= (double)(p * logf(p + 1e-10f));
    }
    sd[tid] = lp;
    __syncthreads();
    for (int s = 128; s > 0; s >>= 1) {
        if (tid < s) sd[tid] += sd[tid + s];
        __syncthreads();
    }

    if (out_size >= ZLEN + 18) {
        if (tid == 0) {
            out[ZLEN + 17] = (float)sd[0];
            double ds = 0.0;
            for (int i = 0; i < 512; ++i) ds += (double)g_partials[i];
            out[ZLEN] = (float)(0.25 * ds / ((double)NPTS * (double)EE));
        }
        if (tid >= 32 && tid < 48)
            out[ZLEN + 1 + (tid - 32)] = (float)(log(2048.0) * 4096.0);
    }
}

// ---------------- launch ----------------
extern "C" void kernel_launch(void* const* d_in, const int* in_sizes, int n_in,
                              void* d_out, int out_size) {
    const float* x  = (const float*)d_in[0];   // [B, CIN, T]
    const float* w  = (const float*)d_in[1];   // [E, CIN]
    const float* pb = (const float*)d_in[2];   // [E]
    const float* em = (const float*)d_in[3];   // [K, E]
    float* out = (float*)d_out;

    static int smem_set = 0;
    if (!smem_set) {
        cudaFuncSetAttribute(k_projmma,
                             cudaFuncAttributeMaxDynamicSharedMemorySize, PTOT);
        smem_set = 1;
    }

    k_init<<<(KK + 255) / 256, 256>>>(em);
    k_wsplit<<<64, 256>>>(w);
    k_projmma<<<BB * (TT / 128), 256, PTOT>>>(x, pb);
    k_dist<<<NPTS / 128, 256>>>(em);
    k_out<<<BB * (TT / 128), 256>>>(em, out);
    k_fin<<<1, 256>>>(out, out_size);
}

// round 8
// speedup vs baseline: 2.8213x; 1.0275x over previous
#include <cuda_runtime.h>
#include <cuda_fp16.h>
#include <math.h>
#include <stdint.h>

#define BB   16
#define CIN  512
#define TT   4096
#define EE   64
#define KK   2048
#define NPTS (BB * TT)        // 65536
#define ZLEN (NPTS * EE)      // 4194304

typedef unsigned long long u64;

// fp16 split of a float2: v = hi + lo elementwise, packed as half2 (u32 bits)
__device__ __forceinline__ void f16s(float2 v, uint32_t& hi, uint32_t& lo) {
    __half2 h = __floats2half2_rn(v.x, v.y);
    float2 hf = __half22float2(h);
    __half2 l = __floats2half2_rn(v.x - hf.x, v.y - hf.y);
    hi = *(uint32_t*)&h;
    lo = *(uint32_t*)&l;
}

// m16n8k16 fp16 MMA, fp32 accumulate
#define MMAF16(c0, c1, c2, c3, a0, a1, a2, a3, b0, b1)                        \
    asm("mma.sync.aligned.m16n8k16.row.col.f32.f16.f16.f32 "                  \
        "{%0,%1,%2,%3}, {%4,%5,%6,%7}, {%8,%9}, {%0,%1,%2,%3};"               \
        : "+f"(c0), "+f"(c1), "+f"(c2), "+f"(c3)                              \
        : "r"(a0), "r"(a1), "r"(a2), "r"(a3), "r"(b0), "r"(b1))

// packed-fragment slot (bytes within a 160B row) for k-pair index l (k=2l)
__device__ __forceinline__ uint32_t fslot(int l) {
    return (uint32_t)((((l >> 3) * 4 + (l & 3)) << 3) + (((l >> 2) & 1) << 2));
}

__device__ __forceinline__ uint32_t smem_u32(const void* p) {
    uint32_t a;
    asm("{ .reg .u64 t; cvta.to.shared.u64 t, %1; cvt.u32.u64 %0, t; }"
        : "=r"(a) : "l"(p));
    return a;
}
__device__ __forceinline__ void cpa16(uint32_t saddr, const void* g) {
    asm volatile("cp.async.cg.shared.global [%0], [%1], 16;"
                 :: "r"(saddr), "l"(g) : "memory");
}
#define CPA_COMMIT() asm volatile("cp.async.commit_group;" ::: "memory")
#define CPA_WAIT1()  asm volatile("cp.async.wait_group 1;" ::: "memory")
#define CPA_WAIT0()  asm volatile("cp.async.wait_group 0;" ::: "memory")

// ---------------- device scratch ----------------
__device__ float    g_h[ZLEN];        // projected features h[n][e]
__device__ __align__(16) float g_enorm[KK];      // ||e_k||^2
__device__ int      g_qidx[NPTS];     // argmin codeword per point
__device__ int      g_counts[KK];     // histogram
__device__ float    g_partials[512];  // per-CTA commitment partials
__device__ uint32_t g_wfh[8 * 64 * 40];   // w fragments hi
__device__ uint32_t g_wfl[8 * 64 * 40];   // w fragments lo
__device__ __align__(16) uint32_t g_ebh[KK * 40];  // codebook fragments hi
__device__ __align__(16) uint32_t g_ebl[KK * 40];  // codebook fragments lo

// ---------------- init: codeword norms + zero counts ----------------
__global__ void k_init(const float* __restrict__ embed) {
    int k = blockIdx.x * blockDim.x + threadIdx.x;
    if (k < KK) {
        const float4* row = (const float4*)(embed + (size_t)k * EE);
        float s = 0.f;
#pragma unroll
        for (int j = 0; j < 16; ++j) {
            float4 v = row[j];
            s += v.x * v.x + v.y * v.y + v.z * v.z + v.w * v.w;
        }
        g_enorm[k] = s;
        g_counts[k] = 0;
    }
}

// ---------------- codebook fragment pre-split (once, ~3us) ----------------
__global__ void k_esplit(const float* __restrict__ embed) {
    int i = blockIdx.x * 256 + threadIdx.x;     // 0..65535
    if (i >= KK * 32) return;
    int k = i >> 5;
    int l = i & 31;
    float2 v = *(const float2*)(embed + (size_t)k * EE + 2 * l);
    uint32_t hi, lo;
    f16s(v, hi, lo);
    uint32_t off = (uint32_t)(k * 40) + (fslot(l) >> 2);
    g_ebh[off] = hi;
    g_ebl[off] = lo;
}

// ---------------- w fragment pre-split (once) ----------------
__global__ void k_wsplit(const float* __restrict__ w) {
    int i = blockIdx.x * 256 + threadIdx.x;     // 0..16383
    if (i >= 8 * 64 * 32) return;
    int ch = i >> 11;
    int e  = (i >> 5) & 63;
    int l  = i & 31;
    float2 v = *(const float2*)(w + (size_t)e * CIN + ch * 64 + 2 * l);
    uint32_t hi, lo;
    f16s(v, hi, lo);
    uint32_t off = (uint32_t)(ch * 64 * 40 + e * 40) + (fslot(l) >> 2);
    g_wfh[off] = hi;
    g_wfl[off] = lo;
}

// ---------------- projection GEMM via fp16 3-split mma.sync ----------------
#define PXS   0
#define PBH   33792
#define PBL   44032
#define PTOT  54272

__global__ __launch_bounds__(256) void k_projmma(const float* __restrict__ x,
                                                 const float* __restrict__ pb) {
    extern __shared__ char sm[];
    float* xs = (float*)(sm + PXS);                 // [64][132]
    unsigned char* sBh = (unsigned char*)(sm + PBH);
    unsigned char* sBl = (unsigned char*)(sm + PBL);

    int tid  = threadIdx.x;
    int wid  = tid >> 5;
    int lane = tid & 31;
    int g = lane >> 2;
    int q = lane & 3;

    int b  = blockIdx.x >> 5;
    int t0 = (blockIdx.x & 31) * 128;
    const float* xb = x + (size_t)b * CIN * TT + t0;

    float acc[8][4];
#pragma unroll
    for (int nb = 0; nb < 8; ++nb)
#pragma unroll
        for (int j = 0; j < 4; ++j) acc[nb][j] = 0.f;

    int m0 = wid * 16 + g;

    for (int ch = 0; ch < 8; ++ch) {
        __syncthreads();
#pragma unroll
        for (int p = 0; p < 8; ++p) {
            int idx = tid + p * 256;
            int c = idx >> 5;
            int f = idx & 31;
            *(float4*)&xs[c * 132 + f * 4] =
                *(const float4*)(xb + (size_t)(ch * 64 + c) * TT + f * 4);
        }
        {
            const uint4* wh = (const uint4*)(g_wfh + ch * 2560);
            const uint4* wl = (const uint4*)(g_wfl + ch * 2560);
#pragma unroll
            for (int p = 0; p < 3; ++p) {
                int i = tid + p * 256;
                if (i < 640) {
                    ((uint4*)sBh)[i] = wh[i];
                    ((uint4*)sBl)[i] = wl[i];
                }
            }
        }
        __syncthreads();

#pragma unroll
        for (int s = 0; s < 4; ++s) {
            int c = s * 16 + 2 * q;
            uint32_t a0h, a0l, a1h, a1l, a2h, a2l, a3h, a3l;
            f16s(make_float2(xs[c * 132 + m0],           xs[(c + 1) * 132 + m0]),     a0h, a0l);
            f16s(make_float2(xs[c * 132 + m0 + 8],       xs[(c + 1) * 132 + m0 + 8]), a1h, a1l);
            f16s(make_float2(xs[(c + 8) * 132 + m0],     xs[(c + 9) * 132 + m0]),     a2h, a2l);
            f16s(make_float2(xs[(c + 8) * 132 + m0 + 8], xs[(c + 9) * 132 + m0 + 8]), a3h, a3l);
#pragma unroll
            for (int nb = 0; nb < 8; ++nb) {
                uint32_t boff = (uint32_t)((nb * 8 + g) * 160 + q * 8 + s * 32);
                uint2 bh = *(const uint2*)(sBh + boff);
                uint2 bl = *(const uint2*)(sBl + boff);
                MMAF16(acc[nb][0], acc[nb][1], acc[nb][2], acc[nb][3],
                       a0h, a1h, a2h, a3h, bh.x, bh.y);
                MMAF16(acc[nb][0], acc[nb][1], acc[nb][2], acc[nb][3],
                       a0h, a1h, a2h, a3h, bl.x, bl.y);
                MMAF16(acc[nb][0], acc[nb][1], acc[nb][2], acc[nb][3],
                       a0l, a1l, a2l, a3l, bh.x, bh.y);
            }
        }
    }

#pragma unroll
    for (int nb = 0; nb < 8; ++nb) {
        float2 bv = *(const float2*)(pb + nb * 8 + 2 * q);
        float2 o0 = make_float2(acc[nb][0] + bv.x, acc[nb][1] + bv.y);
        float2 o1 = make_float2(acc[nb][2] + bv.x, acc[nb][3] + bv.y);
        size_t base = ((size_t)(b * TT + t0 + m0)) * EE + nb * 8 + 2 * q;
        *(float2*)(g_h + base) = o0;
        *(float2*)(g_h + base + 8 * EE) = o1;
    }
}

// ---------------- distance argmin: pre-packed frags + cp.async + 2-way ILP --
__global__ __launch_bounds__(256) void k_dist() {
    __shared__ uint4 sBh[2][640];    // 2 x 10 KB
    __shared__ uint4 sBl[2][640];    // 2 x 10 KB
    __shared__ float sN[2][64];

    int tid  = threadIdx.x;
    int wid  = tid >> 5;
    int lane = tid & 31;
    int g = lane >> 2;
    int q = lane & 3;

    uint32_t a_sbh = smem_u32(sBh);
    uint32_t a_sbl = smem_u32(sBl);
    uint32_t a_sn  = smem_u32(sN);

    int rowA = blockIdx.x * 128 + wid * 16 + g;
    int rowB = rowA + 8;

    // A fragments (hi+lo) once
    uint32_t Ah[4][4], Al[4][4];
#pragma unroll
    for (int s = 0; s < 4; ++s) {
        const float* pA = g_h + (size_t)rowA * EE + s * 16 + 2 * q;
        const float* pB = g_h + (size_t)rowB * EE + s * 16 + 2 * q;
        f16s(*(const float2*)pA,       Ah[s][0], Al[s][0]);
        f16s(*(const float2*)pB,       Ah[s][1], Al[s][1]);
        f16s(*(const float2*)(pA + 8), Ah[s][2], Al[s][2]);
        f16s(*(const float2*)(pB + 8), Ah[s][3], Al[s][3]);
    }

    auto stage = [&](int c, int buf) {
        const uint4* gh = ((const uint4*)g_ebh) + c * 640;
        const uint4* gl = ((const uint4*)g_ebl) + c * 640;
#pragma unroll
        for (int p = 0; p < 3; ++p) {
            int i = tid + p * 256;
            if (i < 640) {
                cpa16(a_sbh + buf * 10240 + i * 16, gh + i);
                cpa16(a_sbl + buf * 10240 + i * 16, gl + i);
            }
        }
        if (tid < 16)
            cpa16(a_sn + buf * 256 + tid * 16,
                  ((const uint4*)(g_enorm + c * 64)) + tid);
        CPA_COMMIT();
    };

    float bestA = 3.4e38f, bestB = 3.4e38f;
    int   bkA = 0, bkB = 0;

    stage(0, 0);

    for (int c = 0; c < 32; ++c) {
        if (c + 1 < 32) { stage(c + 1, (c + 1) & 1); CPA_WAIT1(); }
        else            { CPA_WAIT0(); }
        __syncthreads();

        const unsigned char* bufh = (const unsigned char*)sBh[c & 1];
        const unsigned char* bufl = (const unsigned char*)sBl[c & 1];
        const float* sn = sN[c & 1];

        for (int nb = 0; nb < 64; nb += 16) {
            float c0 = 0.f, c1 = 0.f, c2 = 0.f, c3 = 0.f;
            float d0 = 0.f, d1 = 0.f, d2 = 0.f, d3 = 0.f;
            uint32_t bo0 = (uint32_t)((nb + g) * 160 + q * 8);
            uint32_t bo1 = bo0 + 8 * 160;
#pragma unroll
            for (int s = 0; s < 4; ++s) {
                uint2 bh0 = *(const uint2*)(bufh + bo0 + s * 32);
                uint2 bh1 = *(const uint2*)(bufh + bo1 + s * 32);
                uint2 bl0 = *(const uint2*)(bufl + bo0 + s * 32);
                uint2 bl1 = *(const uint2*)(bufl + bo1 + s * 32);
                MMAF16(c0, c1, c2, c3, Ah[s][0], Ah[s][1], Ah[s][2], Ah[s][3], bh0.x, bh0.y);
                MMAF16(d0, d1, d2, d3, Ah[s][0], Ah[s][1], Ah[s][2], Ah[s][3], bh1.x, bh1.y);
                MMAF16(c0, c1, c2, c3, Ah[s][0], Ah[s][1], Ah[s][2], Ah[s][3], bl0.x, bl0.y);
                MMAF16(d0, d1, d2, d3, Ah[s][0], Ah[s][1], Ah[s][2], Ah[s][3], bl1.x, bl1.y);
                MMAF16(c0, c1, c2, c3, Al[s][0], Al[s][1], Al[s][2], Al[s][3], bh0.x, bh0.y);
                MMAF16(d0, d1, d2, d3, Al[s][0], Al[s][1], Al[s][2], Al[s][3], bh1.x, bh1.y);
            }
            int kb = blockIdx.x * 0 + c * 64 + nb;  // ascending-k order
            float sn0 = sn[nb + 2 * q];
            float sn1 = sn[nb + 2 * q + 1];
            float sn2 = sn[nb + 8 + 2 * q];
            float sn3 = sn[nb + 8 + 2 * q + 1];
            float s0 = fmaf(-2.f, c0, sn0);
            float s1 = fmaf(-2.f, c1, sn1);
            float s2 = fmaf(-2.f, c2, sn0);
            float s3 = fmaf(-2.f, c3, sn1);
            float t0 = fmaf(-2.f, d0, sn2);
            float t1 = fmaf(-2.f, d1, sn3);
            float t2 = fmaf(-2.f, d2, sn2);
            float t3 = fmaf(-2.f, d3, sn3);
            if (s0 < bestA) { bestA = s0; bkA = kb + 2 * q; }
            if (s1 < bestA) { bestA = s1; bkA = kb + 2 * q + 1; }
            if (t0 < bestA) { bestA = t0; bkA = kb + 8 + 2 * q; }
            if (t1 < bestA) { bestA = t1; bkA = kb + 8 + 2 * q + 1; }
            if (s2 < bestB) { bestB = s2; bkB = kb + 2 * q; }
            if (s3 < bestB) { bestB = s3; bkB = kb + 2 * q + 1; }
            if (t2 < bestB) { bestB = t2; bkB = kb + 8 + 2 * q; }
            if (t3 < bestB) { bestB = t3; bkB = kb + 8 + 2 * q + 1; }
        }
        __syncthreads();
    }

    // quad reduce (lanes differing in low 2 bits: same rows, different cols)
#pragma unroll
    for (int off = 1; off <= 2; off <<= 1) {
        float oA = __shfl_xor_sync(0xffffffffu, bestA, off);
        int   kA = __shfl_xor_sync(0xffffffffu, bkA, off);
        float oB = __shfl_xor_sync(0xffffffffu, bestB, off);
        int   kB = __shfl_xor_sync(0xffffffffu, bkB, off);
        if (oA < bestA || (oA == bestA && kA < bkA)) { bestA = oA; bkA = kA; }
        if (oB < bestB || (oB == bestB && kB < bkB)) { bestB = oB; bkB = kB; }
    }
    if (q == 0) {
        g_qidx[rowA] = bkA;
        g_qidx[rowB] = bkB;
    }
}

// ---------------- gather + transpose + reductions ----------------
__global__ __launch_bounds__(256) void k_out(const float* __restrict__ embed,
                                             float* __restrict__ out) {
    __shared__ float zq[128][65];
    __shared__ float red[8];

    int b  = blockIdx.x >> 5;
    int t0 = (blockIdx.x & 31) * 128;
    int tid = threadIdx.x;
    int tl   = tid >> 1;
    int half = tid & 1;
    int n = b * TT + t0 + tl;
    int q = g_qidx[n];

    float lsum = 0.f;
    const float4* ep = (const float4*)(embed + (size_t)q * EE + half * 32);
    const float4* hp = (const float4*)(g_h + (size_t)n * EE + half * 32);
#pragma unroll
    for (int j = 0; j < 8; ++j) {
        float4 z = ep[j];
        float4 hh = hp[j];
        float dx = z.x - hh.x, dy = z.y - hh.y, dz = z.z - hh.z, dw = z.w - hh.w;
        lsum += dx * dx + dy * dy + dz * dz + dw * dw;
        int e = half * 32 + j * 4;
        zq[tl][e + 0] = z.x; zq[tl][e + 1] = z.y;
        zq[tl][e + 2] = z.z; zq[tl][e + 3] = z.w;
    }
    if (half == 0) atomicAdd(&g_counts[q], 1);

#pragma unroll
    for (int s = 16; s > 0; s >>= 1) lsum += __shfl_down_sync(0xffffffffu, lsum, s);
    if ((tid & 31) == 0) red[tid >> 5] = lsum;
    __syncthreads();
    if (tid == 0) {
        float s = 0.f;
#pragma unroll
        for (int i = 0; i < 8; ++i) s += red[i];
        g_partials[blockIdx.x] = s;
    }

#pragma unroll
    for (int p = 0; p < 32; ++p) {
        int idx = p * 256 + tid;
        int e = idx >> 7;
        int t = idx & 127;
        out[((size_t)b * EE + e) * TT + t0 + t] = zq[t][e];
    }
}

// ---------------- finalize scalars ----------------
__global__ void k_fin(float* __restrict__ out, int out_size) {
    __shared__ double sd[256];
    int tid = threadIdx.x;

    double lp = 0.0;
    for (int k = tid; k < KK; k += 256) {
        float p = (float)g_counts[k] / (float)NPTS;
        lp -= (double)(p * logf(p + 1e-10f));
    }
    sd[tid] = lp;
    __syncthreads();
    for (int s = 128; s > 0; s >>= 1) {
        if (tid < s) sd[tid] += sd[tid + s];
        __syncthreads();
    }

    if (out_size >= ZLEN + 18) {
        if (tid == 0) {
            out[ZLEN + 17] = (float)sd[0];
            double ds = 0.0;
            for (int i = 0; i < 512; ++i) ds += (double)g_partials[i];
            out[ZLEN] = (float)(0.25 * ds / ((double)NPTS * (double)EE));
        }
        if (tid >= 32 && tid < 48)
            out[ZLEN + 1 + (tid - 32)] = (float)(log(2048.0) * 4096.0);
    }
}

// ---------------- launch ----------------
extern "C" void kernel_launch(void* const* d_in, const int* in_sizes, int n_in,
                              void* d_out, int out_size) {
    const float* x  = (const float*)d_in[0];   // [B, CIN, T]
    const float* w  = (const float*)d_in[1];   // [E, CIN]
    const float* pb = (const float*)d_in[2];   // [E]
    const float* em = (const float*)d_in[3];   // [K, E]
    float* out = (float*)d_out;

    static int smem_set = 0;
    if (!smem_set) {
        cudaFuncSetAttribute(k_projmma,
                             cudaFuncAttributeMaxDynamicSharedMemorySize, PTOT);
        smem_set = 1;
    }

    k_init<<<(KK + 255) / 256, 256>>>(em);
    k_esplit<<<256, 256>>>(em);
    k_wsplit<<<64, 256>>>(w);
    k_projmma<<<BB * (TT / 128), 256, PTOT>>>(x, pb);
    k_dist<<<NPTS / 128, 256>>>();
    k_out<<<BB * (TT / 128), 256>>>(em, out);
    k_fin<<<1, 256>>>(out, out_size);
}

// round 9
// speedup vs baseline: 3.1963x; 1.1329x over previous
#include <cuda_runtime.h>
#include <cuda_fp16.h>
#include <math.h>
#include <stdint.h>

#define BB   16
#define CIN  512
#define TT   4096
#define EE   64
#define KK   2048
#define NPTS (BB * TT)        // 65536
#define ZLEN (NPTS * EE)      // 4194304

// fp16 split of a float2: v = hi + lo elementwise, packed as half2 (u32 bits)
__device__ __forceinline__ void f16s(float2 v, uint32_t& hi, uint32_t& lo) {
    __half2 h = __floats2half2_rn(v.x, v.y);
    float2 hf = __half22float2(h);
    __half2 l = __floats2half2_rn(v.x - hf.x, v.y - hf.y);
    hi = *(uint32_t*)&h;
    lo = *(uint32_t*)&l;
}

// m16n8k16 fp16 MMA, fp32 accumulate
#define MMAF16(c0, c1, c2, c3, a0, a1, a2, a3, b0, b1)                        \
    asm("mma.sync.aligned.m16n8k16.row.col.f32.f16.f16.f32 "                  \
        "{%0,%1,%2,%3}, {%4,%5,%6,%7}, {%8,%9}, {%0,%1,%2,%3};"               \
        : "+f"(c0), "+f"(c1), "+f"(c2), "+f"(c3)                              \
        : "r"(a0), "r"(a1), "r"(a2), "r"(a3), "r"(b0), "r"(b1))

// packed-fragment slot (bytes within a 160B row) for k-pair index l (k=2l)
__device__ __forceinline__ uint32_t fslot(int l) {
    return (uint32_t)((((l >> 3) * 4 + (l & 3)) << 3) + (((l >> 2) & 1) << 2));
}

__device__ __forceinline__ uint32_t smem_u32(const void* p) {
    uint32_t a;
    asm("{ .reg .u64 t; cvta.to.shared.u64 t, %1; cvt.u32.u64 %0, t; }"
        : "=r"(a) : "l"(p));
    return a;
}
__device__ __forceinline__ void cpa16(uint32_t saddr, const void* g) {
    asm volatile("cp.async.cg.shared.global [%0], [%1], 16;"
                 :: "r"(saddr), "l"(g) : "memory");
}
#define CPA_COMMIT() asm volatile("cp.async.commit_group;" ::: "memory")
#define CPA_WAIT0()  asm volatile("cp.async.wait_group 0;" ::: "memory")

// ---------------- device scratch ----------------
__device__ float    g_h[ZLEN];                   // projected features h[n][e]
__device__ __align__(16) float g_enorm[KK];      // ||e_k||^2
__device__ int      g_qidx[NPTS];                // argmin codeword per point
__device__ int      g_counts[KK];                // histogram
__device__ float    g_partials[512];             // per-CTA commitment partials
__device__ __align__(16) uint32_t g_wfh[8 * 64 * 40];   // w fragments hi
__device__ __align__(16) uint32_t g_wfl[8 * 64 * 40];   // w fragments lo
__device__ __align__(16) uint32_t g_ebh[KK * 40];        // codebook frags hi
__device__ __align__(16) uint32_t g_ebl[KK * 40];        // codebook frags lo

// ---------------- prep: norms + counts + both fragment pre-splits ----------
__global__ void k_prep(const float* __restrict__ embed,
                       const float* __restrict__ w) {
    int i = blockIdx.x * 256 + threadIdx.x;      // 0..65535

    // codebook fragment split (KK*32 = 65536 items)
    {
        int k = i >> 5;
        int l = i & 31;
        float2 v = *(const float2*)(embed + (size_t)k * EE + 2 * l);
        uint32_t hi, lo;
        f16s(v, hi, lo);
        uint32_t off = (uint32_t)(k * 40) + (fslot(l) >> 2);
        g_ebh[off] = hi;
        g_ebl[off] = lo;
    }
    // w fragment split (8*64*32 = 16384 items)
    if (i < 8 * 64 * 32) {
        int ch = i >> 11;
        int e  = (i >> 5) & 63;
        int l  = i & 31;
        float2 v = *(const float2*)(w + (size_t)e * CIN + ch * 64 + 2 * l);
        uint32_t hi, lo;
        f16s(v, hi, lo);
        uint32_t off = (uint32_t)(ch * 64 * 40 + e * 40) + (fslot(l) >> 2);
        g_wfh[off] = hi;
        g_wfl[off] = lo;
    }
    // norms + zero counts (KK items)
    if (i < KK) {
        const float4* row = (const float4*)(embed + (size_t)i * EE);
        float s = 0.f;
#pragma unroll
        for (int j = 0; j < 16; ++j) {
            float4 v = row[j];
            s += v.x * v.x + v.y * v.y + v.z * v.z + v.w * v.w;
        }
        g_enorm[i] = s;
        g_counts[i] = 0;
    }
}

// ---------------- projection GEMM: cp.async double-buffered ----------------
#define PX0   0
#define PX1   33792
#define PBH0  67584
#define PBH1  77824
#define PBL0  88064
#define PBL1  98304
#define PTOT  108544

__global__ __launch_bounds__(256) void k_projmma(const float* __restrict__ x,
                                                 const float* __restrict__ pb) {
    extern __shared__ char sm[];
    uint32_t sbase = smem_u32(sm);

    int tid  = threadIdx.x;
    int wid  = tid >> 5;
    int lane = tid & 31;
    int g = lane >> 2;
    int q = lane & 3;

    int b  = blockIdx.x >> 5;
    int t0 = (blockIdx.x & 31) * 128;
    const float* xb = x + (size_t)b * CIN * TT + t0;

    float acc[8][4];
#pragma unroll
    for (int nb = 0; nb < 8; ++nb)
#pragma unroll
        for (int j = 0; j < 4; ++j) acc[nb][j] = 0.f;

    int m0 = wid * 16 + g;

    auto stage_p = [&](int ch, int buf) {
        uint32_t xa = sbase + (buf ? PX1 : PX0);
#pragma unroll
        for (int p = 0; p < 8; ++p) {
            int idx = tid + p * 256;
            int c = idx >> 5;
            int f = idx & 31;
            cpa16(xa + (uint32_t)(c * 132 + f * 4) * 4,
                  xb + (size_t)(ch * 64 + c) * TT + f * 4);
        }
        const uint4* wh = (const uint4*)(g_wfh + ch * 2560);
        const uint4* wl = (const uint4*)(g_wfl + ch * 2560);
        uint32_t ha = sbase + (buf ? PBH1 : PBH0);
        uint32_t la = sbase + (buf ? PBL1 : PBL0);
#pragma unroll
        for (int p = 0; p < 3; ++p) {
            int i = tid + p * 256;
            if (i < 640) {
                cpa16(ha + i * 16, wh + i);
                cpa16(la + i * 16, wl + i);
            }
        }
        CPA_COMMIT();
    };

    stage_p(0, 0);

    for (int ch = 0; ch < 8; ++ch) {
        CPA_WAIT0();
        __syncthreads();
        if (ch + 1 < 8) stage_p(ch + 1, (ch + 1) & 1);

        const float* xs = (const float*)(sm + ((ch & 1) ? PX1 : PX0));
        const unsigned char* sBh = (const unsigned char*)(sm + ((ch & 1) ? PBH1 : PBH0));
        const unsigned char* sBl = (const unsigned char*)(sm + ((ch & 1) ? PBL1 : PBL0));

#pragma unroll
        for (int s = 0; s < 4; ++s) {
            int c = s * 16 + 2 * q;
            uint32_t a0h, a0l, a1h, a1l, a2h, a2l, a3h, a3l;
            f16s(make_float2(xs[c * 132 + m0],           xs[(c + 1) * 132 + m0]),     a0h, a0l);
            f16s(make_float2(xs[c * 132 + m0 + 8],       xs[(c + 1) * 132 + m0 + 8]), a1h, a1l);
            f16s(make_float2(xs[(c + 8) * 132 + m0],     xs[(c + 9) * 132 + m0]),     a2h, a2l);
            f16s(make_float2(xs[(c + 8) * 132 + m0 + 8], xs[(c + 9) * 132 + m0 + 8]), a3h, a3l);
#pragma unroll
            for (int nb = 0; nb < 8; ++nb) {
                uint32_t boff = (uint32_t)((nb * 8 + g) * 160 + q * 8 + s * 32);
                uint2 bh = *(const uint2*)(sBh + boff);
                uint2 bl = *(const uint2*)(sBl + boff);
                MMAF16(acc[nb][0], acc[nb][1], acc[nb][2], acc[nb][3],
                       a0h, a1h, a2h, a3h, bh.x, bh.y);
                MMAF16(acc[nb][0], acc[nb][1], acc[nb][2], acc[nb][3],
                       a0h, a1h, a2h, a3h, bl.x, bl.y);
                MMAF16(acc[nb][0], acc[nb][1], acc[nb][2], acc[nb][3],
                       a0l, a1l, a2l, a3l, bh.x, bh.y);
            }
        }
    }

#pragma unroll
    for (int nb = 0; nb < 8; ++nb) {
        float2 bv = *(const float2*)(pb + nb * 8 + 2 * q);
        float2 o0 = make_float2(acc[nb][0] + bv.x, acc[nb][1] + bv.y);
        float2 o1 = make_float2(acc[nb][2] + bv.x, acc[nb][3] + bv.y);
        size_t base = ((size_t)(b * TT + t0 + m0)) * EE + nb * 8 + 2 * q;
        *(float2*)(g_h + base) = o0;
        *(float2*)(g_h + base + 8 * EE) = o1;
    }
}

// ---------------- distance argmin: 1 sync/chunk, 4-way ILP, fused loss -----
__global__ __launch_bounds__(256) void k_dist() {
    __shared__ uint4 sBh[2][640];    // 2 x 10 KB
    __shared__ uint4 sBl[2][640];    // 2 x 10 KB
    __shared__ float sN[2][64];
    __shared__ float red[8];

    int tid  = threadIdx.x;
    int wid  = tid >> 5;
    int lane = tid & 31;
    int g = lane >> 2;
    int q = lane & 3;

    uint32_t a_sbh = smem_u32(sBh);
    uint32_t a_sbl = smem_u32(sBl);
    uint32_t a_sn  = smem_u32(sN);

    int rowA = blockIdx.x * 128 + wid * 16 + g;
    int rowB = rowA + 8;

    // A fragments (hi+lo) once; accumulate partial ||h||^2 along the way
    uint32_t Ah[4][4], Al[4][4];
    float hnA = 0.f, hnB = 0.f;
#pragma unroll
    for (int s = 0; s < 4; ++s) {
        const float* pA = g_h + (size_t)rowA * EE + s * 16 + 2 * q;
        const float* pB = g_h + (size_t)rowB * EE + s * 16 + 2 * q;
        float2 vA0 = *(const float2*)pA;
        float2 vB0 = *(const float2*)pB;
        float2 vA1 = *(const float2*)(pA + 8);
        float2 vB1 = *(const float2*)(pB + 8);
        hnA += vA0.x * vA0.x + vA0.y * vA0.y + vA1.x * vA1.x + vA1.y * vA1.y;
        hnB += vB0.x * vB0.x + vB0.y * vB0.y + vB1.x * vB1.x + vB1.y * vB1.y;
        f16s(vA0, Ah[s][0], Al[s][0]);
        f16s(vB0, Ah[s][1], Al[s][1]);
        f16s(vA1, Ah[s][2], Al[s][2]);
        f16s(vB1, Ah[s][3], Al[s][3]);
    }

    auto stage = [&](int c, int buf) {
        const uint4* gh = ((const uint4*)g_ebh) + c * 640;
        const uint4* gl = ((const uint4*)g_ebl) + c * 640;
#pragma unroll
        for (int p = 0; p < 3; ++p) {
            int i = tid + p * 256;
            if (i < 640) {
                cpa16(a_sbh + buf * 10240 + i * 16, gh + i);
                cpa16(a_sbl + buf * 10240 + i * 16, gl + i);
            }
        }
        if (tid < 16)
            cpa16(a_sn + buf * 256 + tid * 16,
                  ((const uint4*)(g_enorm + c * 64)) + tid);
        CPA_COMMIT();
    };

    float bestA = 3.4e38f, bestB = 3.4e38f;
    int   bkA = 0, bkB = 0;

    stage(0, 0);

    for (int c = 0; c < 32; ++c) {
        CPA_WAIT0();
        __syncthreads();
        if (c + 1 < 32) stage(c + 1, (c + 1) & 1);

        const unsigned char* bufh = (const unsigned char*)sBh[c & 1];
        const unsigned char* bufl = (const unsigned char*)sBl[c & 1];
        const float* sn = sN[c & 1];

#pragma unroll
        for (int oi = 0; oi < 2; ++oi) {
            // 4 independent accumulator chains over n-blocks oi*32 + {0,8,16,24}
            float a0[4], a1[4], a2[4], a3[4];
#pragma unroll
            for (int j = 0; j < 4; ++j) { a0[j] = a1[j] = a2[j] = a3[j] = 0.f; }
#pragma unroll
            for (int s = 0; s < 4; ++s) {
#pragma unroll
                for (int j = 0; j < 4; ++j) {
                    uint32_t bo = (uint32_t)((oi * 32 + j * 8 + g) * 160
                                             + q * 8 + s * 32);
                    uint2 bh = *(const uint2*)(bufh + bo);
                    uint2 bl = *(const uint2*)(bufl + bo);
                    MMAF16(a0[j], a1[j], a2[j], a3[j],
                           Ah[s][0], Ah[s][1], Ah[s][2], Ah[s][3], bh.x, bh.y);
                    MMAF16(a0[j], a1[j], a2[j], a3[j],
                           Ah[s][0], Ah[s][1], Ah[s][2], Ah[s][3], bl.x, bl.y);
                    MMAF16(a0[j], a1[j], a2[j], a3[j],
                           Al[s][0], Al[s][1], Al[s][2], Al[s][3], bh.x, bh.y);
                }
            }
#pragma unroll
            for (int j = 0; j < 4; ++j) {
                int nb = oi * 32 + j * 8;
                int kb = c * 64 + nb;
                float sn0 = sn[nb + 2 * q];
                float sn1 = sn[nb + 2 * q + 1];
                float s0 = fmaf(-2.f, a0[j], sn0);
                float s1 = fmaf(-2.f, a1[j], sn1);
                float s2 = fmaf(-2.f, a2[j], sn0);
                float s3 = fmaf(-2.f, a3[j], sn1);
                if (s0 < bestA) { bestA = s0; bkA = kb + 2 * q; }
                if (s1 < bestA) { bestA = s1; bkA = kb + 2 * q + 1; }
                if (s2 < bestB) { bestB = s2; bkB = kb + 2 * q; }
                if (s3 < bestB) { bestB = s3; bkB = kb + 2 * q + 1; }
            }
        }
    }

    // quad reduce best/index + hnorm partials
#pragma unroll
    for (int off = 1; off <= 2; off <<= 1) {
        float oA = __shfl_xor_sync(0xffffffffu, bestA, off);
        int   kA = __shfl_xor_sync(0xffffffffu, bkA, off);
        float oB = __shfl_xor_sync(0xffffffffu, bestB, off);
        int   kB = __shfl_xor_sync(0xffffffffu, bkB, off);
        hnA += __shfl_xor_sync(0xffffffffu, hnA, off);
        hnB += __shfl_xor_sync(0xffffffffu, hnB, off);
        if (oA < bestA || (oA == bestA && kA < bkA)) { bestA = oA; bkA = kA; }
        if (oB < bestB || (oB == bestB && kB < bkB)) { bestB = oB; bkB = kB; }
    }
    if (q == 0) {
        g_qidx[rowA] = bkA;
        g_qidx[rowB] = bkB;
    }

    // commitment partial: d^2 = best + ||h||^2 (exact identity, small fp err)
    float contrib = (q == 0) ? (bestA + hnA + bestB + hnB) : 0.f;
#pragma unroll
    for (int off = 16; off > 0; off >>= 1)
        contrib += __shfl_xor_sync(0xffffffffu, contrib, off);
    if (lane == 0) red[wid] = contrib;
    __syncthreads();
    if (tid == 0) {
        float s = 0.f;
#pragma unroll
        for (int i = 0; i < 8; ++i) s += red[i];
        g_partials[blockIdx.x] = s;
    }
}

// ---------------- gather + transpose (loss moved to k_dist) ----------------
__global__ __launch_bounds__(256) void k_out(const float* __restrict__ embed,
                                             float* __restrict__ out) {
    __shared__ float zq[128][65];

    int b  = blockIdx.x >> 5;
    int t0 = (blockIdx.x & 31) * 128;
    int tid = threadIdx.x;
    int tl   = tid >> 1;
    int half = tid & 1;
    int n = b * TT + t0 + tl;
    int q = g_qidx[n];

    const float4* ep = (const float4*)(embed + (size_t)q * EE + half * 32);
#pragma unroll
    for (int j = 0; j < 8; ++j) {
        float4 z = ep[j];
        int e = half * 32 + j * 4;
        zq[tl][e + 0] = z.x; zq[tl][e + 1] = z.y;
        zq[tl][e + 2] = z.z; zq[tl][e + 3] = z.w;
    }
    if (half == 0) atomicAdd(&g_counts[q], 1);
    __syncthreads();

#pragma unroll
    for (int p = 0; p < 32; ++p) {
        int idx = p * 256 + tid;
        int e = idx >> 7;
        int t = idx & 127;
        out[((size_t)b * EE + e) * TT + t0 + t] = zq[t][e];
    }
}

// ---------------- finalize scalars ----------------
__global__ void k_fin(float* __restrict__ out, int out_size) {
    __shared__ double sd[256];
    int tid = threadIdx.x;

    double lp = 0.0;
    for (int k = tid; k < KK; k += 256) {
        float p = (float)g_counts[k] / (float)NPTS;
        lp -= (double)(p * logf(p + 1e-10f));
    }
    sd[tid] = lp;
    __syncthreads();
    for (int s = 128; s > 0; s >>= 1) {
        if (tid < s) sd[tid] += sd[tid + s];
        __syncthreads();
    }

    if (out_size >= ZLEN + 18) {
        if (tid == 0) {
            out[ZLEN + 17] = (float)sd[0];
            double ds = 0.0;
            for (int i = 0; i < 512; ++i) ds += (double)g_partials[i];
            out[ZLEN] = (float)(0.25 * ds / ((double)NPTS * (double)EE));
        }
        if (tid >= 32 && tid < 48)
            out[ZLEN + 1 + (tid - 32)] = (float)(log(2048.0) * 4096.0);
    }
}

// ---------------- launch ----------------
extern "C" void kernel_launch(void* const* d_in, const int* in_sizes, int n_in,
                              void* d_out, int out_size) {
    const float* x  = (const float*)d_in[0];   // [B, CIN, T]
    const float* w  = (const float*)d_in[1];   // [E, CIN]
    const float* pb = (const float*)d_in[2];   // [E]
    const float* em = (const float*)d_in[3];   // [K, E]
    float* out = (float*)d_out;

    static int smem_set = 0;
    if (!smem_set) {
        cudaFuncSetAttribute(k_projmma,
                             cudaFuncAttributeMaxDynamicSharedMemorySize, PTOT);
        smem_set = 1;
    }

    k_prep<<<256, 256>>>(em, w);
    k_projmma<<<BB * (TT / 128), 256, PTOT>>>(x, pb);
    k_dist<<<NPTS / 128, 256>>>();
    k_out<<<BB * (TT / 128), 256>>>(em, out);
    k_fin<<<1, 256>>>(out, out_size);
}

// round 10
// speedup vs baseline: 3.5616x; 1.1143x over previous
#include <cuda_runtime.h>
#include <cuda_fp16.h>
#include <math.h>
#include <stdint.h>

#define BB   16
#define CIN  512
#define TT   4096
#define EE   64
#define KK   2048
#define NPTS (BB * TT)        // 65536
#define ZLEN (NPTS * EE)      // 4194304

// fp16 split of a float2: v = hi + lo elementwise, packed as half2 (u32 bits)
__device__ __forceinline__ void f16s(float2 v, uint32_t& hi, uint32_t& lo) {
    __half2 h = __floats2half2_rn(v.x, v.y);
    float2 hf = __half22float2(h);
    __half2 l = __floats2half2_rn(v.x - hf.x, v.y - hf.y);
    hi = *(uint32_t*)&h;
    lo = *(uint32_t*)&l;
}

// m16n8k16 fp16 MMA, fp32 accumulate
#define MMAF16(c0, c1, c2, c3, a0, a1, a2, a3, b0, b1)                        \
    asm("mma.sync.aligned.m16n8k16.row.col.f32.f16.f16.f32 "                  \
        "{%0,%1,%2,%3}, {%4,%5,%6,%7}, {%8,%9}, {%0,%1,%2,%3};"               \
        : "+f"(c0), "+f"(c1), "+f"(c2), "+f"(c3)                              \
        : "r"(a0), "r"(a1), "r"(a2), "r"(a3), "r"(b0), "r"(b1))

// packed-fragment slot (bytes within a 160B row) for k-pair index l (k=2l)
__device__ __forceinline__ uint32_t fslot(int l) {
    return (uint32_t)((((l >> 3) * 4 + (l & 3)) << 3) + (((l >> 2) & 1) << 2));
}

__device__ __forceinline__ uint32_t smem_u32(const void* p) {
    uint32_t a;
    asm("{ .reg .u64 t; cvta.to.shared.u64 t, %1; cvt.u32.u64 %0, t; }"
        : "=r"(a) : "l"(p));
    return a;
}
__device__ __forceinline__ void cpa16(uint32_t saddr, const void* g) {
    asm volatile("cp.async.cg.shared.global [%0], [%1], 16;"
                 :: "r"(saddr), "l"(g) : "memory");
}
#define CPA_COMMIT() asm volatile("cp.async.commit_group;" ::: "memory")
#define CPA_WAIT0()  asm volatile("cp.async.wait_group 0;" ::: "memory")

// ---------------- device scratch ----------------
__device__ float    g_h[ZLEN];                   // projected features h[n][e]
__device__ __align__(16) float g_enorm[KK];      // ||e_k||^2
__device__ int      g_counts[KK];                // histogram
__device__ float    g_partials[256];             // per-CTA commitment partials
__device__ __align__(16) uint32_t g_wfh[8 * 64 * 40];   // w fragments hi
__device__ __align__(16) uint32_t g_wfl[8 * 64 * 40];   // w fragments lo
__device__ __align__(16) uint32_t g_ebh[KK * 40];        // codebook frags hi
__device__ __align__(16) uint32_t g_ebl[KK * 40];        // codebook frags lo

// ---------------- prep: norms + counts + both fragment pre-splits ----------
__global__ void k_prep(const float* __restrict__ embed,
                       const float* __restrict__ w) {
    int i = blockIdx.x * 256 + threadIdx.x;      // 0..65535

    {   // codebook fragment split (KK*32 = 65536 items)
        int k = i >> 5;
        int l = i & 31;
        float2 v = *(const float2*)(embed + (size_t)k * EE + 2 * l);
        uint32_t hi, lo;
        f16s(v, hi, lo);
        uint32_t off = (uint32_t)(k * 40) + (fslot(l) >> 2);
        g_ebh[off] = hi;
        g_ebl[off] = lo;
    }
    if (i < 8 * 64 * 32) {    // w fragment split
        int ch = i >> 11;
        int e  = (i >> 5) & 63;
        int l  = i & 31;
        float2 v = *(const float2*)(w + (size_t)e * CIN + ch * 64 + 2 * l);
        uint32_t hi, lo;
        f16s(v, hi, lo);
        uint32_t off = (uint32_t)(ch * 64 * 40 + e * 40) + (fslot(l) >> 2);
        g_wfh[off] = hi;
        g_wfl[off] = lo;
    }
    if (i < KK) {             // norms + zero counts
        const float4* row = (const float4*)(embed + (size_t)i * EE);
        float s = 0.f;
#pragma unroll
        for (int j = 0; j < 16; ++j) {
            float4 v = row[j];
            s += v.x * v.x + v.y * v.y + v.z * v.z + v.w * v.w;
        }
        g_enorm[i] = s;
        g_counts[i] = 0;
    }
}

// ---------------- projection GEMM: cp.async double-buffered ----------------
#define PX0   0
#define PX1   33792
#define PBH0  67584
#define PBH1  77824
#define PBL0  88064
#define PBL1  98304
#define PTOT  108544

__global__ __launch_bounds__(256) void k_projmma(const float* __restrict__ x,
                                                 const float* __restrict__ pb) {
    extern __shared__ char sm[];
    uint32_t sbase = smem_u32(sm);

    int tid  = threadIdx.x;
    int wid  = tid >> 5;
    int lane = tid & 31;
    int g = lane >> 2;
    int q = lane & 3;

    int b  = blockIdx.x >> 5;
    int t0 = (blockIdx.x & 31) * 128;
    const float* xb = x + (size_t)b * CIN * TT + t0;

    float acc[8][4];
#pragma unroll
    for (int nb = 0; nb < 8; ++nb)
#pragma unroll
        for (int j = 0; j < 4; ++j) acc[nb][j] = 0.f;

    int m0 = wid * 16 + g;

    auto stage_p = [&](int ch, int buf) {
        uint32_t xa = sbase + (buf ? PX1 : PX0);
#pragma unroll
        for (int p = 0; p < 8; ++p) {
            int idx = tid + p * 256;
            int c = idx >> 5;
            int f = idx & 31;
            cpa16(xa + (uint32_t)(c * 132 + f * 4) * 4,
                  xb + (size_t)(ch * 64 + c) * TT + f * 4);
        }
        const uint4* wh = (const uint4*)(g_wfh + ch * 2560);
        const uint4* wl = (const uint4*)(g_wfl + ch * 2560);
        uint32_t ha = sbase + (buf ? PBH1 : PBH0);
        uint32_t la = sbase + (buf ? PBL1 : PBL0);
#pragma unroll
        for (int p = 0; p < 3; ++p) {
            int i = tid + p * 256;
            if (i < 640) {
                cpa16(ha + i * 16, wh + i);
                cpa16(la + i * 16, wl + i);
            }
        }
        CPA_COMMIT();
    };

    stage_p(0, 0);

    for (int ch = 0; ch < 8; ++ch) {
        CPA_WAIT0();
        __syncthreads();
        if (ch + 1 < 8) stage_p(ch + 1, (ch + 1) & 1);

        const float* xs = (const float*)(sm + ((ch & 1) ? PX1 : PX0));
        const unsigned char* sBh = (const unsigned char*)(sm + ((ch & 1) ? PBH1 : PBH0));
        const unsigned char* sBl = (const unsigned char*)(sm + ((ch & 1) ? PBL1 : PBL0));

#pragma unroll
        for (int s = 0; s < 4; ++s) {
            int c = s * 16 + 2 * q;
            uint32_t a0h, a0l, a1h, a1l, a2h, a2l, a3h, a3l;
            f16s(make_float2(xs[c * 132 + m0],           xs[(c + 1) * 132 + m0]),     a0h, a0l);
            f16s(make_float2(xs[c * 132 + m0 + 8],       xs[(c + 1) * 132 + m0 + 8]), a1h, a1l);
            f16s(make_float2(xs[(c + 8) * 132 + m0],     xs[(c + 9) * 132 + m0]),     a2h, a2l);
            f16s(make_float2(xs[(c + 8) * 132 + m0 + 8], xs[(c + 9) * 132 + m0 + 8]), a3h, a3l);
#pragma unroll
            for (int nb = 0; nb < 8; ++nb) {
                uint32_t boff = (uint32_t)((nb * 8 + g) * 160 + q * 8 + s * 32);
                uint2 bh = *(const uint2*)(sBh + boff);
                uint2 bl = *(const uint2*)(sBl + boff);
                MMAF16(acc[nb][0], acc[nb][1], acc[nb][2], acc[nb][3],
                       a0h, a1h, a2h, a3h, bh.x, bh.y);
                MMAF16(acc[nb][0], acc[nb][1], acc[nb][2], acc[nb][3],
                       a0h, a1h, a2h, a3h, bl.x, bl.y);
                MMAF16(acc[nb][0], acc[nb][1], acc[nb][2], acc[nb][3],
                       a0l, a1l, a2l, a3l, bh.x, bh.y);
            }
        }
    }

#pragma unroll
    for (int nb = 0; nb < 8; ++nb) {
        float2 bv = *(const float2*)(pb + nb * 8 + 2 * q);
        float2 o0 = make_float2(acc[nb][0] + bv.x, acc[nb][1] + bv.y);
        float2 o1 = make_float2(acc[nb][2] + bv.x, acc[nb][3] + bv.y);
        size_t base = ((size_t)(b * TT + t0 + m0)) * EE + nb * 8 + 2 * q;
        *(float2*)(g_h + base) = o0;
        *(float2*)(g_h + base + 8 * EE) = o1;
    }
}

// ---------------- fused distance argmin + loss + counts + gather/output ----
// 256 points/CTA (2 m16 tiles/warp), 256 CTAs (single wave). Codebook in
// 64-codeword double-buffered chunks (pre-packed fragments, cp.async).
// Epilogue: argmin -> counts + commitment (d2 = best + ||h||^2) + gather
// embed rows via smem transpose and write out[b][e][t] directly.
__global__ __launch_bounds__(256) void k_dist(const float* __restrict__ embed,
                                              float* __restrict__ out) {
    __shared__ __align__(16) unsigned char SM[41504];
    // [0,20480)      sBh[2][640] uint4       (epilogue overlay: zq[128][65])
    // [20480,40960)  sBl[2][640]             (epilogue overlay: sq[256] @33280)
    // [40960,41472)  sN[2][64]
    // [41472,41504)  red[8]
    uint32_t a_sbh = smem_u32(SM);
    uint32_t a_sbl = a_sbh + 20480;
    uint32_t a_sn  = a_sbh + 40960;
    float* red = (float*)(SM + 41472);

    int tid  = threadIdx.x;
    int wid  = tid >> 5;
    int lane = tid & 31;
    int g = lane >> 2;
    int q = lane & 3;

    int b  = blockIdx.x >> 4;
    int t0 = (blockIdx.x & 15) * 256;
    int base = blockIdx.x * 256 + wid * 32;

    // ---- A fragments for 2 tiles (rows base+0..15, base+16..31) ----
    uint32_t A0h[4][4], A0l[4][4], A1h[4][4], A1l[4][4];
    float hn0 = 0.f, hn1 = 0.f, hn2 = 0.f, hn3 = 0.f;
#pragma unroll
    for (int s = 0; s < 4; ++s) {
        const float* p0 = g_h + (size_t)(base + g) * EE + s * 16 + 2 * q;
        float2 v00 = *(const float2*)p0;
        float2 v01 = *(const float2*)(p0 + 8);
        float2 v10 = *(const float2*)(p0 + 8 * EE);
        float2 v11 = *(const float2*)(p0 + 8 * EE + 8);
        float2 v20 = *(const float2*)(p0 + 16 * EE);
        float2 v21 = *(const float2*)(p0 + 16 * EE + 8);
        float2 v30 = *(const float2*)(p0 + 24 * EE);
        float2 v31 = *(const float2*)(p0 + 24 * EE + 8);
        hn0 += v00.x * v00.x + v00.y * v00.y + v01.x * v01.x + v01.y * v01.y;
        hn1 += v10.x * v10.x + v10.y * v10.y + v11.x * v11.x + v11.y * v11.y;
        hn2 += v20.x * v20.x + v20.y * v20.y + v21.x * v21.x + v21.y * v21.y;
        hn3 += v30.x * v30.x + v30.y * v30.y + v31.x * v31.x + v31.y * v31.y;
        f16s(v00, A0h[s][0], A0l[s][0]);
        f16s(v10, A0h[s][1], A0l[s][1]);
        f16s(v01, A0h[s][2], A0l[s][2]);
        f16s(v11, A0h[s][3], A0l[s][3]);
        f16s(v20, A1h[s][0], A1l[s][0]);
        f16s(v30, A1h[s][1], A1l[s][1]);
        f16s(v21, A1h[s][2], A1l[s][2]);
        f16s(v31, A1h[s][3], A1l[s][3]);
    }

    auto stage = [&](int c, int buf) {
        const uint4* gh = ((const uint4*)g_ebh) + c * 640;
        const uint4* gl = ((const uint4*)g_ebl) + c * 640;
#pragma unroll
        for (int p = 0; p < 3; ++p) {
            int i = tid + p * 256;
            if (i < 640) {
                cpa16(a_sbh + buf * 10240 + i * 16, gh + i);
                cpa16(a_sbl + buf * 10240 + i * 16, gl + i);
            }
        }
        if (tid < 16)
            cpa16(a_sn + buf * 256 + tid * 16,
                  ((const uint4*)(g_enorm + c * 64)) + tid);
        CPA_COMMIT();
    };

    float bA0 = 3.4e38f, bB0 = 3.4e38f, bA1 = 3.4e38f, bB1 = 3.4e38f;
    int   kA0 = 0, kB0 = 0, kA1 = 0, kB1 = 0;

    stage(0, 0);

    for (int c = 0; c < 32; ++c) {
        CPA_WAIT0();
        __syncthreads();
        if (c + 1 < 32) stage(c + 1, (c + 1) & 1);

        const unsigned char* bufh = SM + (c & 1) * 10240;
        const unsigned char* bufl = SM + 20480 + (c & 1) * 10240;
        const float* sn = (const float*)(SM + 40960 + (c & 1) * 256);

#pragma unroll
        for (int nb = 0; nb < 8; ++nb) {
            float c0 = 0.f, c1 = 0.f, c2 = 0.f, c3 = 0.f;
            float d0 = 0.f, d1 = 0.f, d2 = 0.f, d3 = 0.f;
            uint32_t bo = (uint32_t)((nb * 8 + g) * 160 + q * 8);
#pragma unroll
            for (int s = 0; s < 4; ++s) {
                uint2 bh = *(const uint2*)(bufh + bo + s * 32);
                uint2 bl = *(const uint2*)(bufl + bo + s * 32);
                MMAF16(c0, c1, c2, c3, A0h[s][0], A0h[s][1], A0h[s][2], A0h[s][3], bh.x, bh.y);
                MMAF16(d0, d1, d2, d3, A1h[s][0], A1h[s][1], A1h[s][2], A1h[s][3], bh.x, bh.y);
                MMAF16(c0, c1, c2, c3, A0h[s][0], A0h[s][1], A0h[s][2], A0h[s][3], bl.x, bl.y);
                MMAF16(d0, d1, d2, d3, A1h[s][0], A1h[s][1], A1h[s][2], A1h[s][3], bl.x, bl.y);
                MMAF16(c0, c1, c2, c3, A0l[s][0], A0l[s][1], A0l[s][2], A0l[s][3], bh.x, bh.y);
                MMAF16(d0, d1, d2, d3, A1l[s][0], A1l[s][1], A1l[s][2], A1l[s][3], bh.x, bh.y);
            }
            int kb = c * 64 + nb * 8;
            float sn0 = sn[nb * 8 + 2 * q];
            float sn1 = sn[nb * 8 + 2 * q + 1];
            float s0 = fmaf(-2.f, c0, sn0);
            float s1 = fmaf(-2.f, c1, sn1);
            float s2 = fmaf(-2.f, c2, sn0);
            float s3 = fmaf(-2.f, c3, sn1);
            float u0 = fmaf(-2.f, d0, sn0);
            float u1 = fmaf(-2.f, d1, sn1);
            float u2 = fmaf(-2.f, d2, sn0);
            float u3 = fmaf(-2.f, d3, sn1);
            if (s0 < bA0) { bA0 = s0; kA0 = kb + 2 * q; }
            if (s1 < bA0) { bA0 = s1; kA0 = kb + 2 * q + 1; }
            if (s2 < bB0) { bB0 = s2; kB0 = kb + 2 * q; }
            if (s3 < bB0) { bB0 = s3; kB0 = kb + 2 * q + 1; }
            if (u0 < bA1) { bA1 = u0; kA1 = kb + 2 * q; }
            if (u1 < bA1) { bA1 = u1; kA1 = kb + 2 * q + 1; }
            if (u2 < bB1) { bB1 = u2; kB1 = kb + 2 * q; }
            if (u3 < bB1) { bB1 = u3; kB1 = kb + 2 * q + 1; }
        }
    }

    // quad reduce (lanes differing in low 2 bits: same rows, different cols)
#pragma unroll
    for (int off = 1; off <= 2; off <<= 1) {
        float o; int k;
        o = __shfl_xor_sync(0xffffffffu, bA0, off);
        k = __shfl_xor_sync(0xffffffffu, kA0, off);
        if (o < bA0 || (o == bA0 && k < kA0)) { bA0 = o; kA0 = k; }
        o = __shfl_xor_sync(0xffffffffu, bB0, off);
        k = __shfl_xor_sync(0xffffffffu, kB0, off);
        if (o < bB0 || (o == bB0 && k < kB0)) { bB0 = o; kB0 = k; }
        o = __shfl_xor_sync(0xffffffffu, bA1, off);
        k = __shfl_xor_sync(0xffffffffu, kA1, off);
        if (o < bA1 || (o == bA1 && k < kA1)) { bA1 = o; kA1 = k; }
        o = __shfl_xor_sync(0xffffffffu, bB1, off);
        k = __shfl_xor_sync(0xffffffffu, kB1, off);
        if (o < bB1 || (o == bB1 && k < kB1)) { bB1 = o; kB1 = k; }
        hn0 += __shfl_xor_sync(0xffffffffu, hn0, off);
        hn1 += __shfl_xor_sync(0xffffffffu, hn1, off);
        hn2 += __shfl_xor_sync(0xffffffffu, hn2, off);
        hn3 += __shfl_xor_sync(0xffffffffu, hn3, off);
    }

    __syncthreads();   // all fragment-buffer reads complete before overlay

    int* sq = (int*)(SM + 33280);   // 256 point indices
    if (q == 0) {
        sq[wid * 32 + g]      = kA0;
        sq[wid * 32 + 8 + g]  = kB0;
        sq[wid * 32 + 16 + g] = kA1;
        sq[wid * 32 + 24 + g] = kB1;
        atomicAdd(&g_counts[kA0], 1);
        atomicAdd(&g_counts[kB0], 1);
        atomicAdd(&g_counts[kA1], 1);
        atomicAdd(&g_counts[kB1], 1);
    }

    // commitment partial: d^2 = best + ||h||^2
    float contrib = (q == 0)
        ? (bA0 + hn0) + (bB0 + hn1) + (bA1 + hn2) + (bB1 + hn3) : 0.f;
#pragma unroll
    for (int off = 16; off > 0; off >>= 1)
        contrib += __shfl_xor_sync(0xffffffffu, contrib, off);
    if (lane == 0) red[wid] = contrib;
    __syncthreads();
    if (tid == 0) {
        float s = 0.f;
#pragma unroll
        for (int i = 0; i < 8; ++i) s += red[i];
        g_partials[blockIdx.x] = s;
    }

    // ---- gather + transpose + output, 2 passes of 128 t ----
    float* zq = (float*)SM;          // [128][65]
    for (int p = 0; p < 2; ++p) {
        __syncthreads();
        int tl = tid >> 1;
        int hf = tid & 1;
        int qi = sq[p * 128 + tl];
        const float4* ep = (const float4*)(embed + (size_t)qi * EE + hf * 32);
#pragma unroll
        for (int j = 0; j < 8; ++j) {
            float4 z = ep[j];
            int e = hf * 32 + j * 4;
            zq[tl * 65 + e + 0] = z.x;
            zq[tl * 65 + e + 1] = z.y;
            zq[tl * 65 + e + 2] = z.z;
            zq[tl * 65 + e + 3] = z.w;
        }
        __syncthreads();
#pragma unroll
        for (int i = 0; i < 32; ++i) {
            int idx = i * 256 + tid;
            int e  = idx >> 7;
            int tt = idx & 127;
            out[((size_t)(b * EE + e)) * TT + t0 + p * 128 + tt] =
                zq[tt * 65 + e];
        }
    }
}

// ---------------- finalize scalars ----------------
__global__ void k_fin(float* __restrict__ out, int out_size) {
    __shared__ double sd[256];
    int tid = threadIdx.x;

    double lp = 0.0;
    for (int k = tid; k < KK; k += 256) {
        float p = (float)g_counts[k] / (float)NPTS;
        lp -= (double)(p * logf(p + 1e-10f));
    }
    sd[tid] = lp;
    __syncthreads();
    for (int s = 128; s > 0; s >>= 1) {
        if (tid < s) sd[tid] += sd[tid + s];
        __syncthreads();
    }

    if (out_size >= ZLEN + 18) {
        if (tid == 0) {
            out[ZLEN + 17] = (float)sd[0];
            double ds = 0.0;
            for (int i = 0; i < 256; ++i) ds += (double)g_partials[i];
            out[ZLEN] = (float)(0.25 * ds / ((double)NPTS * (double)EE));
        }
        if (tid >= 32 && tid < 48)
            out[ZLEN + 1 + (tid - 32)] = (float)(log(2048.0) * 4096.0);
    }
}

// ---------------- launch ----------------
extern "C" void kernel_launch(void* const* d_in, const int* in_sizes, int n_in,
                              void* d_out, int out_size) {
    const float* x  = (const float*)d_in[0];   // [B, CIN, T]
    const float* w  = (const float*)d_in[1];   // [E, CIN]
    const float* pb = (const float*)d_in[2];   // [E]
    const float* em = (const float*)d_in[3];   // [K, E]
    float* out = (float*)d_out;

    static int smem_set = 0;
    if (!smem_set) {
        cudaFuncSetAttribute(k_projmma,
                             cudaFuncAttributeMaxDynamicSharedMemorySize, PTOT);
        smem_set = 1;
    }

    k_prep<<<256, 256>>>(em, w);
    k_projmma<<<BB * (TT / 128), 256, PTOT>>>(x, pb);
    k_dist<<<NPTS / 256, 256>>>(em, out);
    k_fin<<<1, 256>>>(out, out_size);
}

// round 11
// speedup vs baseline: 3.9388x; 1.1059x over previous
#include <cuda_runtime.h>
#include <cuda_fp16.h>
#include <math.h>
#include <stdint.h>

#define BB   16
#define CIN  512
#define TT   4096
#define EE   64
#define KK   2048
#define NPTS (BB * TT)        // 65536
#define ZLEN (NPTS * EE)      // 4194304

// fp16 split of a float2: v = hi + lo elementwise, packed as half2 (u32 bits)
__device__ __forceinline__ void f16s(float2 v, uint32_t& hi, uint32_t& lo) {
    __half2 h = __floats2half2_rn(v.x, v.y);
    float2 hf = __half22float2(h);
    __half2 l = __floats2half2_rn(v.x - hf.x, v.y - hf.y);
    hi = *(uint32_t*)&h;
    lo = *(uint32_t*)&l;
}

// m16n8k16 fp16 MMA, fp32 accumulate
#define MMAF16(c0, c1, c2, c3, a0, a1, a2, a3, b0, b1)                        \
    asm("mma.sync.aligned.m16n8k16.row.col.f32.f16.f16.f32 "                  \
        "{%0,%1,%2,%3}, {%4,%5,%6,%7}, {%8,%9}, {%0,%1,%2,%3};"               \
        : "+f"(c0), "+f"(c1), "+f"(c2), "+f"(c3)                              \
        : "r"(a0), "r"(a1), "r"(a2), "r"(a3), "r"(b0), "r"(b1))

// packed-fragment slot (bytes within a 160B row) for k-pair index l (k=2l)
__device__ __forceinline__ uint32_t fslot(int l) {
    return (uint32_t)((((l >> 3) * 4 + (l & 3)) << 3) + (((l >> 2) & 1) << 2));
}

__device__ __forceinline__ uint32_t smem_u32(const void* p) {
    uint32_t a;
    asm("{ .reg .u64 t; cvta.to.shared.u64 t, %1; cvt.u32.u64 %0, t; }"
        : "=r"(a) : "l"(p));
    return a;
}
__device__ __forceinline__ void cpa16(uint32_t saddr, const void* g) {
    asm volatile("cp.async.cg.shared.global [%0], [%1], 16;"
                 :: "r"(saddr), "l"(g) : "memory");
}
#define CPA_COMMIT() asm volatile("cp.async.commit_group;" ::: "memory")
#define CPA_WAIT0()  asm volatile("cp.async.wait_group 0;" ::: "memory")

// ---------------- device scratch ----------------
__device__ float    g_h[ZLEN];                   // projected features h[n][e]
__device__ __align__(16) float g_enorm[KK];      // ||e_k||^2
__device__ int      g_counts[KK];                // histogram
__device__ float    g_partials[256];             // per-CTA commitment partials
__device__ __align__(16) uint32_t g_wfh[8 * 64 * 40];   // w fragments hi
__device__ __align__(16) uint32_t g_wfl[8 * 64 * 40];   // w fragments lo
__device__ __align__(16) uint32_t g_ebh[KK * 40];        // codebook frags hi
__device__ __align__(16) uint32_t g_ebl[KK * 40];        // codebook frags lo

// ---------------- prep: norms + counts + both fragment pre-splits ----------
__global__ void k_prep(const float* __restrict__ embed,
                       const float* __restrict__ w) {
    int i = blockIdx.x * 256 + threadIdx.x;      // 0..65535

    {   // codebook fragment split (KK*32 = 65536 items)
        int k = i >> 5;
        int l = i & 31;
        float2 v = *(const float2*)(embed + (size_t)k * EE + 2 * l);
        uint32_t hi, lo;
        f16s(v, hi, lo);
        uint32_t off = (uint32_t)(k * 40) + (fslot(l) >> 2);
        g_ebh[off] = hi;
        g_ebl[off] = lo;
    }
    if (i < 8 * 64 * 32) {    // w fragment split
        int ch = i >> 11;
        int e  = (i >> 5) & 63;
        int l  = i & 31;
        float2 v = *(const float2*)(w + (size_t)e * CIN + ch * 64 + 2 * l);
        uint32_t hi, lo;
        f16s(v, hi, lo);
        uint32_t off = (uint32_t)(ch * 64 * 40 + e * 40) + (fslot(l) >> 2);
        g_wfh[off] = hi;
        g_wfl[off] = lo;
    }
    if (i < KK) {             // norms + zero counts
        const float4* row = (const float4*)(embed + (size_t)i * EE);
        float s = 0.f;
#pragma unroll
        for (int j = 0; j < 16; ++j) {
            float4 v = row[j];
            s += v.x * v.x + v.y * v.y + v.z * v.z + v.w * v.w;
        }
        g_enorm[i] = s;
        g_counts[i] = 0;
    }
}

// ---------------- projection GEMM: cp.async double-buffered ----------------
#define PX0   0
#define PX1   33792
#define PBH0  67584
#define PBH1  77824
#define PBL0  88064
#define PBL1  98304
#define PTOT  108544

__global__ __launch_bounds__(256) void k_projmma(const float* __restrict__ x,
                                                 const float* __restrict__ pb) {
    extern __shared__ char sm[];
    uint32_t sbase = smem_u32(sm);

    int tid  = threadIdx.x;
    int wid  = tid >> 5;
    int lane = tid & 31;
    int g = lane >> 2;
    int q = lane & 3;

    int b  = blockIdx.x >> 5;
    int t0 = (blockIdx.x & 31) * 128;
    const float* xb = x + (size_t)b * CIN * TT + t0;

    float acc[8][4];
#pragma unroll
    for (int nb = 0; nb < 8; ++nb)
#pragma unroll
        for (int j = 0; j < 4; ++j) acc[nb][j] = 0.f;

    int m0 = wid * 16 + g;

    auto stage_p = [&](int ch, int buf) {
        uint32_t xa = sbase + (buf ? PX1 : PX0);
#pragma unroll
        for (int p = 0; p < 8; ++p) {
            int idx = tid + p * 256;
            int c = idx >> 5;
            int f = idx & 31;
            cpa16(xa + (uint32_t)(c * 132 + f * 4) * 4,
                  xb + (size_t)(ch * 64 + c) * TT + f * 4);
        }
        const uint4* wh = (const uint4*)(g_wfh + ch * 2560);
        const uint4* wl = (const uint4*)(g_wfl + ch * 2560);
        uint32_t ha = sbase + (buf ? PBH1 : PBH0);
        uint32_t la = sbase + (buf ? PBL1 : PBL0);
#pragma unroll
        for (int p = 0; p < 3; ++p) {
            int i = tid + p * 256;
            if (i < 640) {
                cpa16(ha + i * 16, wh + i);
                cpa16(la + i * 16, wl + i);
            }
        }
        CPA_COMMIT();
    };

    stage_p(0, 0);

    for (int ch = 0; ch < 8; ++ch) {
        CPA_WAIT0();
        __syncthreads();
        if (ch + 1 < 8) stage_p(ch + 1, (ch + 1) & 1);

        const float* xs = (const float*)(sm + ((ch & 1) ? PX1 : PX0));
        const unsigned char* sBh = (const unsigned char*)(sm + ((ch & 1) ? PBH1 : PBH0));
        const unsigned char* sBl = (const unsigned char*)(sm + ((ch & 1) ? PBL1 : PBL0));

#pragma unroll
        for (int s = 0; s < 4; ++s) {
            int c = s * 16 + 2 * q;
            uint32_t a0h, a0l, a1h, a1l, a2h, a2l, a3h, a3l;
            f16s(make_float2(xs[c * 132 + m0],           xs[(c + 1) * 132 + m0]),     a0h, a0l);
            f16s(make_float2(xs[c * 132 + m0 + 8],       xs[(c + 1) * 132 + m0 + 8]), a1h, a1l);
            f16s(make_float2(xs[(c + 8) * 132 + m0],     xs[(c + 9) * 132 + m0]),     a2h, a2l);
            f16s(make_float2(xs[(c + 8) * 132 + m0 + 8], xs[(c + 9) * 132 + m0 + 8]), a3h, a3l);
#pragma unroll
            for (int nb = 0; nb < 8; ++nb) {
                uint32_t boff = (uint32_t)((nb * 8 + g) * 160 + q * 8 + s * 32);
                uint2 bh = *(const uint2*)(sBh + boff);
                uint2 bl = *(const uint2*)(sBl + boff);
                MMAF16(acc[nb][0], acc[nb][1], acc[nb][2], acc[nb][3],
                       a0h, a1h, a2h, a3h, bh.x, bh.y);
                MMAF16(acc[nb][0], acc[nb][1], acc[nb][2], acc[nb][3],
                       a0h, a1h, a2h, a3h, bl.x, bl.y);
                MMAF16(acc[nb][0], acc[nb][1], acc[nb][2], acc[nb][3],
                       a0l, a1l, a2l, a3l, bh.x, bh.y);
            }
        }
    }

#pragma unroll
    for (int nb = 0; nb < 8; ++nb) {
        float2 bv = *(const float2*)(pb + nb * 8 + 2 * q);
        float2 o0 = make_float2(acc[nb][0] + bv.x, acc[nb][1] + bv.y);
        float2 o1 = make_float2(acc[nb][2] + bv.x, acc[nb][3] + bv.y);
        size_t base = ((size_t)(b * TT + t0 + m0)) * EE + nb * 8 + 2 * q;
        *(float2*)(g_h + base) = o0;
        *(float2*)(g_h + base + 8 * EE) = o1;
    }
}

// ---------------- fused distance argmin + loss + counts + gather/output ----
__global__ __launch_bounds__(256) void k_dist(const float* __restrict__ embed,
                                              float* __restrict__ out) {
    __shared__ __align__(16) unsigned char SM[41504];
    uint32_t a_sbh = smem_u32(SM);
    uint32_t a_sbl = a_sbh + 20480;
    uint32_t a_sn  = a_sbh + 40960;
    float* red = (float*)(SM + 41472);

    int tid  = threadIdx.x;
    int wid  = tid >> 5;
    int lane = tid & 31;
    int g = lane >> 2;
    int q = lane & 3;

    int b  = blockIdx.x >> 4;
    int t0 = (blockIdx.x & 15) * 256;
    int base = blockIdx.x * 256 + wid * 32;

    // ---- A fragments for 2 tiles (rows base+0..15, base+16..31) ----
    uint32_t A0h[4][4], A0l[4][4], A1h[4][4], A1l[4][4];
    float hn0 = 0.f, hn1 = 0.f, hn2 = 0.f, hn3 = 0.f;
#pragma unroll
    for (int s = 0; s < 4; ++s) {
        const float* p0 = g_h + (size_t)(base + g) * EE + s * 16 + 2 * q;
        float2 v00 = *(const float2*)p0;
        float2 v01 = *(const float2*)(p0 + 8);
        float2 v10 = *(const float2*)(p0 + 8 * EE);
        float2 v11 = *(const float2*)(p0 + 8 * EE + 8);
        float2 v20 = *(const float2*)(p0 + 16 * EE);
        float2 v21 = *(const float2*)(p0 + 16 * EE + 8);
        float2 v30 = *(const float2*)(p0 + 24 * EE);
        float2 v31 = *(const float2*)(p0 + 24 * EE + 8);
        hn0 += v00.x * v00.x + v00.y * v00.y + v01.x * v01.x + v01.y * v01.y;
        hn1 += v10.x * v10.x + v10.y * v10.y + v11.x * v11.x + v11.y * v11.y;
        hn2 += v20.x * v20.x + v20.y * v20.y + v21.x * v21.x + v21.y * v21.y;
        hn3 += v30.x * v30.x + v30.y * v30.y + v31.x * v31.x + v31.y * v31.y;
        f16s(v00, A0h[s][0], A0l[s][0]);
        f16s(v10, A0h[s][1], A0l[s][1]);
        f16s(v01, A0h[s][2], A0l[s][2]);
        f16s(v11, A0h[s][3], A0l[s][3]);
        f16s(v20, A1h[s][0], A1l[s][0]);
        f16s(v30, A1h[s][1], A1l[s][1]);
        f16s(v21, A1h[s][2], A1l[s][2]);
        f16s(v31, A1h[s][3], A1l[s][3]);
    }

    auto stage = [&](int c, int buf) {
        const uint4* gh = ((const uint4*)g_ebh) + c * 640;
        const uint4* gl = ((const uint4*)g_ebl) + c * 640;
#pragma unroll
        for (int p = 0; p < 3; ++p) {
            int i = tid + p * 256;
            if (i < 640) {
                cpa16(a_sbh + buf * 10240 + i * 16, gh + i);
                cpa16(a_sbl + buf * 10240 + i * 16, gl + i);
            }
        }
        if (tid < 16)
            cpa16(a_sn + buf * 256 + tid * 16,
                  ((const uint4*)(g_enorm + c * 64)) + tid);
        CPA_COMMIT();
    };

    float bA0 = 3.4e38f, bB0 = 3.4e38f, bA1 = 3.4e38f, bB1 = 3.4e38f;
    int   kA0 = 0, kB0 = 0, kA1 = 0, kB1 = 0;

    stage(0, 0);

    for (int c = 0; c < 32; ++c) {
        CPA_WAIT0();
        __syncthreads();
        if (c + 1 < 32) stage(c + 1, (c + 1) & 1);

        const unsigned char* bufh = SM + (c & 1) * 10240;
        const unsigned char* bufl = SM + 20480 + (c & 1) * 10240;
        const float* sn = (const float*)(SM + 40960 + (c & 1) * 256);

#pragma unroll
        for (int nb = 0; nb < 8; ++nb) {
            float c0 = 0.f, c1 = 0.f, c2 = 0.f, c3 = 0.f;
            float d0 = 0.f, d1 = 0.f, d2 = 0.f, d3 = 0.f;
            uint32_t bo = (uint32_t)((nb * 8 + g) * 160 + q * 8);
#pragma unroll
            for (int s = 0; s < 4; ++s) {
                uint2 bh = *(const uint2*)(bufh + bo + s * 32);
                uint2 bl = *(const uint2*)(bufl + bo + s * 32);
                MMAF16(c0, c1, c2, c3, A0h[s][0], A0h[s][1], A0h[s][2], A0h[s][3], bh.x, bh.y);
                MMAF16(d0, d1, d2, d3, A1h[s][0], A1h[s][1], A1h[s][2], A1h[s][3], bh.x, bh.y);
                MMAF16(c0, c1, c2, c3, A0h[s][0], A0h[s][1], A0h[s][2], A0h[s][3], bl.x, bl.y);
                MMAF16(d0, d1, d2, d3, A1h[s][0], A1h[s][1], A1h[s][2], A1h[s][3], bl.x, bl.y);
                MMAF16(c0, c1, c2, c3, A0l[s][0], A0l[s][1], A0l[s][2], A0l[s][3], bh.x, bh.y);
                MMAF16(d0, d1, d2, d3, A1l[s][0], A1l[s][1], A1l[s][2], A1l[s][3], bh.x, bh.y);
            }
            int kb = c * 64 + nb * 8;
            float sn0 = sn[nb * 8 + 2 * q];
            float sn1 = sn[nb * 8 + 2 * q + 1];
            float s0 = fmaf(-2.f, c0, sn0);
            float s1 = fmaf(-2.f, c1, sn1);
            float s2 = fmaf(-2.f, c2, sn0);
            float s3 = fmaf(-2.f, c3, sn1);
            float u0 = fmaf(-2.f, d0, sn0);
            float u1 = fmaf(-2.f, d1, sn1);
            float u2 = fmaf(-2.f, d2, sn0);
            float u3 = fmaf(-2.f, d3, sn1);
            if (s0 < bA0) { bA0 = s0; kA0 = kb + 2 * q; }
            if (s1 < bA0) { bA0 = s1; kA0 = kb + 2 * q + 1; }
            if (s2 < bB0) { bB0 = s2; kB0 = kb + 2 * q; }
            if (s3 < bB0) { bB0 = s3; kB0 = kb + 2 * q + 1; }
            if (u0 < bA1) { bA1 = u0; kA1 = kb + 2 * q; }
            if (u1 < bA1) { bA1 = u1; kA1 = kb + 2 * q + 1; }
            if (u2 < bB1) { bB1 = u2; kB1 = kb + 2 * q; }
            if (u3 < bB1) { bB1 = u3; kB1 = kb + 2 * q + 1; }
        }
    }

#pragma unroll
    for (int off = 1; off <= 2; off <<= 1) {
        float o; int k;
        o = __shfl_xor_sync(0xffffffffu, bA0, off);
        k = __shfl_xor_sync(0xffffffffu, kA0, off);
        if (o < bA0 || (o == bA0 && k < kA0)) { bA0 = o; kA0 = k; }
        o = __shfl_xor_sync(0xffffffffu, bB0, off);
        k = __shfl_xor_sync(0xffffffffu, kB0, off);
        if (o < bB0 || (o == bB0 && k < kB0)) { bB0 = o; kB0 = k; }
        o = __shfl_xor_sync(0xffffffffu, bA1, off);
        k = __shfl_xor_sync(0xffffffffu, kA1, off);
        if (o < bA1 || (o == bA1 && k < kA1)) { bA1 = o; kA1 = k; }
        o = __shfl_xor_sync(0xffffffffu, bB1, off);
        k = __shfl_xor_sync(0xffffffffu, kB1, off);
        if (o < bB1 || (o == bB1 && k < kB1)) { bB1 = o; kB1 = k; }
        hn0 += __shfl_xor_sync(0xffffffffu, hn0, off);
        hn1 += __shfl_xor_sync(0xffffffffu, hn1, off);
        hn2 += __shfl_xor_sync(0xffffffffu, hn2, off);
        hn3 += __shfl_xor_sync(0xffffffffu, hn3, off);
    }

    __syncthreads();   // all fragment-buffer reads complete before overlay

    int* sq = (int*)(SM + 33280);   // 256 point indices
    if (q == 0) {
        sq[wid * 32 + g]      = kA0;
        sq[wid * 32 + 8 + g]  = kB0;
        sq[wid * 32 + 16 + g] = kA1;
        sq[wid * 32 + 24 + g] = kB1;
        atomicAdd(&g_counts[kA0], 1);
        atomicAdd(&g_counts[kB0], 1);
        atomicAdd(&g_counts[kA1], 1);
        atomicAdd(&g_counts[kB1], 1);
    }

    float contrib = (q == 0)
        ? (bA0 + hn0) + (bB0 + hn1) + (bA1 + hn2) + (bB1 + hn3) : 0.f;
#pragma unroll
    for (int off = 16; off > 0; off >>= 1)
        contrib += __shfl_xor_sync(0xffffffffu, contrib, off);
    if (lane == 0) red[wid] = contrib;
    __syncthreads();
    if (tid == 0) {
        float s = 0.f;
#pragma unroll
        for (int i = 0; i < 8; ++i) s += red[i];
        g_partials[blockIdx.x] = s;
    }

    // ---- gather + transpose + output, 2 passes of 128 t ----
    float* zq = (float*)SM;          // [128][65]
    for (int p = 0; p < 2; ++p) {
        __syncthreads();
        int tl = tid >> 1;
        int hf = tid & 1;
        int qi = sq[p * 128 + tl];
        const float4* ep = (const float4*)(embed + (size_t)qi * EE + hf * 32);
#pragma unroll
        for (int j = 0; j < 8; ++j) {
            float4 z = ep[j];
            int e = hf * 32 + j * 4;
            zq[tl * 65 + e + 0] = z.x;
            zq[tl * 65 + e + 1] = z.y;
            zq[tl * 65 + e + 2] = z.z;
            zq[tl * 65 + e + 3] = z.w;
        }
        __syncthreads();
#pragma unroll
        for (int i = 0; i < 32; ++i) {
            int idx = i * 256 + tid;
            int e  = idx >> 7;
            int tt = idx & 127;
            out[((size_t)(b * EE + e)) * TT + t0 + p * 128 + tt] =
                zq[tt * 65 + e];
        }
    }
}

// ---------------- finalize scalars: fully parallel, float ----------------
__global__ __launch_bounds__(1024) void k_fin(float* __restrict__ out,
                                              int out_size) {
    __shared__ float slp[32], scm[32];
    int tid = threadIdx.x;

    float lp = 0.f;
#pragma unroll
    for (int k = tid; k < KK; k += 1024) {
        float p = (float)g_counts[k] * (1.f / (float)NPTS);
        lp -= p * logf(p + 1e-10f);
    }
    float cm = (tid < 256) ? g_partials[tid] : 0.f;

#pragma unroll
    for (int o = 16; o > 0; o >>= 1) {
        lp += __shfl_xor_sync(0xffffffffu, lp, o);
        cm += __shfl_xor_sync(0xffffffffu, cm, o);
    }
    if ((tid & 31) == 0) { slp[tid >> 5] = lp; scm[tid >> 5] = cm; }
    __syncthreads();

    if (tid < 32) {
        lp = slp[tid];
        cm = scm[tid];
#pragma unroll
        for (int o = 16; o > 0; o >>= 1) {
            lp += __shfl_xor_sync(0xffffffffu, lp, o);
            cm += __shfl_xor_sync(0xffffffffu, cm, o);
        }
        if (tid == 0 && out_size >= ZLEN + 18) {
            out[ZLEN + 17] = lp;
            out[ZLEN] = 0.25f * cm / ((float)NPTS * (float)EE);
        }
    }
    if (out_size >= ZLEN + 18 && tid >= 64 && tid < 80)
        out[ZLEN + 1 + (tid - 64)] = (float)(log(2048.0) * 4096.0);
}

// ---------------- launch ----------------
extern "C" void kernel_launch(void* const* d_in, const int* in_sizes, int n_in,
                              void* d_out, int out_size) {
    const float* x  = (const float*)d_in[0];   // [B, CIN, T]
    const float* w  = (const float*)d_in[1];   // [E, CIN]
    const float* pb = (const float*)d_in[2];   // [E]
    const float* em = (const float*)d_in[3];   // [K, E]
    float* out = (float*)d_out;

    static int smem_set = 0;
    if (!smem_set) {
        cudaFuncSetAttribute(k_projmma,
                             cudaFuncAttributeMaxDynamicSharedMemorySize, PTOT);
        smem_set = 1;
    }

    k_prep<<<256, 256>>>(em, w);
    k_projmma<<<BB * (TT / 128), 256, PTOT>>>(x, pb);
    k_dist<<<NPTS / 256, 256>>>(em, out);
    k_fin<<<1, 1024>>>(out, out_size);
}